// round 2
// baseline (speedup 1.0000x reference)
#include <cuda_runtime.h>
#include <math.h>

#define Dm   192
#define HDm  64
#define TOKn 64
#define ROWSn 32
#define NTH  256

// ---------------- transposed (k-major) weight buffers ----------------
__device__ __align__(16) float g_WpT[Dm * Dm];        // [192][192]
__device__ __align__(16) float g_WtT[Dm * Dm];        // [192][192]
__device__ __align__(16) float g_inT[Dm * 3 * Dm];    // [192][576]
__device__ __align__(16) float g_outT[Dm * Dm];       // [192][192]
__device__ __align__(16) float g_f1T[Dm * 2 * Dm];    // [192][384]
__device__ __align__(16) float g_f2T[2 * Dm * Dm];    // [384][192]
__device__ __align__(16) float g_c1T[Dm * Dm];        // [192][192]
__device__ __align__(16) float g_fpT[Dm * 128];       // [192][128]

// src is [R][C] row-major; dst is [C][R] row-major (k-major)
__global__ void transpose_kernel(const float* __restrict__ src,
                                 float* __restrict__ dst, int R, int C) {
    int n = R * C;
    for (int d = blockIdx.x * blockDim.x + threadIdx.x; d < n;
         d += gridDim.x * blockDim.x) {
        int k = d / R;
        int j = d % R;
        dst[d] = src[j * C + k];
    }
}

// ---------------- fused GEMM pass ----------------
// Computes, for 64 output columns [jw0, jw0+64):
//   out[r][j] = (init) + sum_k A[r][ka0 + k] * Wkmajor[kw0 + k][jw0 + j]
// over nk chunks of 64 k each. Thread (tr,tc): rows {tr, tr+16, tr+32, tr+48},
// cols {tc*4 .. tc*4+3}. Dual-weight mode (gW2 != nullptr) selects the weight
// (and bias) by row parity (tr & 1) — used for the perc/tech projection where
// even tokens use Wp and odd tokens use Wt.
__device__ __noinline__ void gemm64(
    const float* __restrict__ sA, int lda, int ka0,
    const float* __restrict__ gW, const float* __restrict__ gW2,
    int ldw, int kw0, int jw0, int nk,
    const float* __restrict__ bias, const float* __restrict__ bias2,
    float* __restrict__ sOut, int ldo, int jo0,
    bool accOut, bool relu, float* __restrict__ sW)
{
    const int tid = threadIdx.x;
    const int tr = tid >> 4;       // 0..15
    const int tc = tid & 15;       // 0..15
    const int c0 = tc * 4;

    __syncthreads();  // order prior writers of sOut / sA against our reads

    float acc[4][4];
    if (accOut) {
#pragma unroll
        for (int i = 0; i < 4; i++) {
            int r = tr + i * 16;
            float4 v = *(const float4*)&sOut[r * ldo + jo0 + c0];
            acc[i][0] = v.x; acc[i][1] = v.y; acc[i][2] = v.z; acc[i][3] = v.w;
        }
    } else {
#pragma unroll
        for (int i = 0; i < 4; i++)
            acc[i][0] = acc[i][1] = acc[i][2] = acc[i][3] = 0.f;
    }
    if (bias) {
        const float* bptr = (bias2 && (tr & 1)) ? bias2 : bias;
        float4 bv = *(const float4*)&bptr[jw0 + c0];
#pragma unroll
        for (int i = 0; i < 4; i++) {
            acc[i][0] += bv.x; acc[i][1] += bv.y;
            acc[i][2] += bv.z; acc[i][3] += bv.w;
        }
    }

    const float* myW = sW + ((gW2 && (tr & 1)) ? 4096 : 0);

    for (int c = 0; c < nk; ++c) {
        __syncthreads();  // previous chunk's tile reads done before overwrite
        {
            const int rr = tid >> 4;
            const int cc = (tid & 15) * 4;
#pragma unroll
            for (int rnd = 0; rnd < 4; ++rnd) {
                int k = rr + rnd * 16;
                float4 v = *(const float4*)&gW[(size_t)(kw0 + c * 64 + k) * ldw + jw0 + cc];
                *(float4*)&sW[k * 64 + cc] = v;
            }
            if (gW2) {
#pragma unroll
                for (int rnd = 0; rnd < 4; ++rnd) {
                    int k = rr + rnd * 16;
                    float4 v = *(const float4*)&gW2[(size_t)(kw0 + c * 64 + k) * ldw + jw0 + cc];
                    *(float4*)&sW[4096 + k * 64 + cc] = v;
                }
            }
        }
        __syncthreads();

        const float* aBase = sA + ka0 + c * 64;
#pragma unroll 4
        for (int kk = 0; kk < 16; ++kk) {
            float4 a4[4], b4[4];
#pragma unroll
            for (int i = 0; i < 4; i++)
                a4[i] = *(const float4*)&aBase[(tr + i * 16) * lda + kk * 4];
#pragma unroll
            for (int u = 0; u < 4; u++)
                b4[u] = *(const float4*)&myW[(kk * 4 + u) * 64 + c0];
#pragma unroll
            for (int i = 0; i < 4; i++) {
                float av0 = a4[i].x, av1 = a4[i].y, av2 = a4[i].z, av3 = a4[i].w;
                acc[i][0] += av0 * b4[0].x; acc[i][1] += av0 * b4[0].y;
                acc[i][2] += av0 * b4[0].z; acc[i][3] += av0 * b4[0].w;
                acc[i][0] += av1 * b4[1].x; acc[i][1] += av1 * b4[1].y;
                acc[i][2] += av1 * b4[1].z; acc[i][3] += av1 * b4[1].w;
                acc[i][0] += av2 * b4[2].x; acc[i][1] += av2 * b4[2].y;
                acc[i][2] += av2 * b4[2].z; acc[i][3] += av2 * b4[2].w;
                acc[i][0] += av3 * b4[3].x; acc[i][1] += av3 * b4[3].y;
                acc[i][2] += av3 * b4[3].z; acc[i][3] += av3 * b4[3].w;
            }
        }
    }

#pragma unroll
    for (int i = 0; i < 4; i++) {
        int r = tr + i * 16;
        float4 v;
        v.x = acc[i][0]; v.y = acc[i][1]; v.z = acc[i][2]; v.w = acc[i][3];
        if (relu) {
            v.x = fmaxf(v.x, 0.f); v.y = fmaxf(v.y, 0.f);
            v.z = fmaxf(v.z, 0.f); v.w = fmaxf(v.w, 0.f);
        }
        *(float4*)&sOut[r * ldo + jo0 + c0] = v;
    }
}

// ---------------- attention for one head ----------------
// sC holds q at +0, k at +4096, v at +8192, each [64 tokens][64]
// writes ctx over the q region. sMisc: 128 floats of softmax weights.
__device__ __forceinline__ void attention_head(float* sC, float* sMisc) {
    const int tid = threadIdx.x;
    const int wid = tid >> 5, lane = tid & 31;
    const float* q = sC;
    const float* k = sC + 4096;
    const float* v = sC + 8192;

#pragma unroll
    for (int ri = 0; ri < 4; ++ri) {
        int r = wid * 4 + ri;            // 32 rows / 8 warps
        int t0 = 2 * r, t1 = 2 * r + 1;
        float q0a = q[t0 * 64 + lane], q0b = q[t0 * 64 + lane + 32];
        float q1a = q[t1 * 64 + lane], q1b = q[t1 * 64 + lane + 32];
        float k0a = k[t0 * 64 + lane], k0b = k[t0 * 64 + lane + 32];
        float k1a = k[t1 * 64 + lane], k1b = k[t1 * 64 + lane + 32];
        float d00 = q0a * k0a + q0b * k0b;
        float d01 = q0a * k1a + q0b * k1b;
        float d10 = q1a * k0a + q1b * k0b;
        float d11 = q1a * k1a + q1b * k1b;
#pragma unroll
        for (int o = 16; o; o >>= 1) {
            d00 += __shfl_xor_sync(0xffffffffu, d00, o);
            d01 += __shfl_xor_sync(0xffffffffu, d01, o);
            d10 += __shfl_xor_sync(0xffffffffu, d10, o);
            d11 += __shfl_xor_sync(0xffffffffu, d11, o);
        }
        if (lane == 0) {
            const float sc = 0.125f;  // 1/sqrt(64)
            d00 *= sc; d01 *= sc; d10 *= sc; d11 *= sc;
            float m0 = fmaxf(d00, d01), m1 = fmaxf(d10, d11);
            float e00 = __expf(d00 - m0), e01 = __expf(d01 - m0);
            float e10 = __expf(d10 - m1), e11 = __expf(d11 - m1);
            float i0 = 1.f / (e00 + e01), i1 = 1.f / (e10 + e11);
            sMisc[t0 * 2 + 0] = e00 * i0; sMisc[t0 * 2 + 1] = e01 * i0;
            sMisc[t1 * 2 + 0] = e10 * i1; sMisc[t1 * 2 + 1] = e11 * i1;
        }
    }
    __syncthreads();  // scores done; q reads done -> safe to overwrite q

#pragma unroll
    for (int e = 0; e < 16; ++e) {
        int idx = tid + e * 256;        // 0..4095
        int t = idx >> 6, j = idx & 63;
        int tb = (t >> 1) * 2;
        float a0 = sMisc[t * 2], a1 = sMisc[t * 2 + 1];
        sC[idx] = a0 * v[tb * 64 + j] + a1 * v[(tb + 1) * 64 + j];
    }
}

// ---------------- layernorm over 64 tokens of 192 ----------------
__device__ __forceinline__ void layernorm64(float* buf, const float* __restrict__ g,
                                            const float* __restrict__ b) {
    const int tid = threadIdx.x;
    const int wid = tid >> 5, lane = tid & 31;
    for (int t = wid; t < TOKn; t += 8) {
        float s = 0.f, sq = 0.f;
        float vv[6];
#pragma unroll
        for (int e = 0; e < 6; e++) {
            float x = buf[t * Dm + lane + e * 32];
            vv[e] = x; s += x; sq += x * x;
        }
#pragma unroll
        for (int o = 16; o; o >>= 1) {
            s += __shfl_xor_sync(0xffffffffu, s, o);
            sq += __shfl_xor_sync(0xffffffffu, sq, o);
        }
        float mu = s * (1.f / Dm);
        float var = sq * (1.f / Dm) - mu * mu;
        float rstd = rsqrtf(var + 1e-5f);
#pragma unroll
        for (int e = 0; e < 6; e++) {
            int j = lane + e * 32;
            buf[t * Dm + j] = (vv[e] - mu) * rstd * g[j] + b[j];
        }
    }
}

// smem layout (floats):
//  [0,     12288)  A : seq / FFN-hidden(low) / z / c1-input etc.
//  [12288, 24576)  C : input acts / q,k,v / FFN-hidden(high) / cls1 out
//  [24576, 36864)  B : attn accum -> x -> x2 -> fp
//  [36864, 45056)  W : weight tiles (2 x 64x64)
//  [45056, 45568)  misc
#define SMEM_FLOATS 45568
#define SMEM_BYTES  (SMEM_FLOATS * 4)

__global__ __launch_bounds__(NTH, 1)
void fusion_kernel(const float* __restrict__ perc, const float* __restrict__ tech,
                   const float* __restrict__ bp,  const float* __restrict__ bt,
                   const float* __restrict__ in_b, const float* __restrict__ out_b,
                   const float* __restrict__ f1b, const float* __restrict__ f2b,
                   const float* __restrict__ ln1g, const float* __restrict__ ln1b,
                   const float* __restrict__ ln2g, const float* __restrict__ ln2b,
                   const float* __restrict__ c1b, const float* __restrict__ c2w,
                   const float* __restrict__ c2b, const float* __restrict__ fpb,
                   float* __restrict__ out, int B)
{
    extern __shared__ float smem[];
    float* sA = smem;
    float* sC = smem + 12288;
    float* sB = smem + 24576;
    float* sW = smem + 36864;
    float* sMisc = smem + 45056;

    const int tid = threadIdx.x;
    const int r0 = blockIdx.x * ROWSn;

    // 1. load inputs -> sC interleaved tokens [64][192] (even=perc, odd=tech)
    for (int idx = tid; idx < TOKn * 48; idx += NTH) {
        int t = idx / 48;
        int c4 = (idx % 48) * 4;
        const float* src = (t & 1) ? tech : perc;
        float4 v = *(const float4*)&src[(size_t)(r0 + (t >> 1)) * Dm + c4];
        *(float4*)&sC[t * Dm + c4] = v;
    }

    // 2. projections -> sA (seq). Dual weights by token parity.
    for (int jg = 0; jg < 3; ++jg)
        gemm64(sC, Dm, 0, g_WpT, g_WtT, Dm, 0, jg * 64, 3,
               bp, bt, sA, Dm, jg * 64, false, false, sW);

    __syncthreads();
    // 3. init sB = seq + out_b  (residual + out-proj bias, pre-added)
    for (int idx = tid; idx < TOKn * Dm; idx += NTH)
        sB[idx] = sA[idx] + out_b[idx % Dm];

    // 4. attention, head by head
    for (int h = 0; h < 3; ++h) {
        for (int part = 0; part < 3; ++part) {
            int jw = part * Dm + h * HDm;
            gemm64(sA, Dm, 0, g_inT, nullptr, 3 * Dm, 0, jw, 3,
                   in_b, nullptr, sC + part * 4096, HDm, 0, false, false, sW);
        }
        __syncthreads();
        attention_head(sC, sMisc);
        for (int jg = 0; jg < 3; ++jg)
            gemm64(sC, HDm, 0, g_outT, nullptr, Dm, h * HDm, jg * 64, 1,
                   nullptr, nullptr, sB, Dm, jg * 64, true, false, sW);
    }
    __syncthreads();
    layernorm64(sB, ln1g, ln1b);   // x in sB

    // 5. FFN1: h = relu(x @ W1^T + b1) -> sA..sC as [64][384]
    for (int jg = 0; jg < 6; ++jg)
        gemm64(sB, Dm, 0, g_f1T, nullptr, 2 * Dm, 0, jg * 64, 3,
               f1b, nullptr, sA, 2 * Dm, jg * 64, false, true, sW);

    // 6. FFN2: sB = x + h @ W2^T + b2 ; LN2
    for (int jg = 0; jg < 3; ++jg)
        gemm64(sA, 2 * Dm, 0, g_f2T, nullptr, Dm, 0, jg * 64, 6,
               f2b, nullptr, sB, Dm, jg * 64, true, false, sW);
    __syncthreads();
    layernorm64(sB, ln2g, ln2b);   // x2 in sB
    __syncthreads();

    // 7. z = mean over the 2 tokens -> sA rows 0..31; zero rows 32..63
    for (int idx = tid; idx < TOKn * Dm; idx += NTH) {
        int r = idx / Dm, j = idx % Dm;
        sA[idx] = (r < ROWSn) ? 0.5f * (sB[(2 * r) * Dm + j] + sB[(2 * r + 1) * Dm + j])
                              : 0.f;
    }

    // 8. cls1 = relu(z @ W^T + b) -> sC
    for (int jg = 0; jg < 3; ++jg)
        gemm64(sA, Dm, 0, g_c1T, nullptr, Dm, 0, jg * 64, 3,
               c1b, nullptr, sC, Dm, jg * 64, false, true, sW);
    __syncthreads();

    // 9. logits + sigmoid -> out[c*B + row]
    if (tid < 96) {
        int r = tid / 3, c = tid % 3;
        float s = c2b[c];
        const float* w = c2w + c * Dm;
        const float* x = sC + r * Dm;
#pragma unroll 8
        for (int kk = 0; kk < Dm; ++kk) s += x[kk] * w[kk];
        out[(size_t)c * B + r0 + r] = 1.f / (1.f + __expf(-s));
    }

    // 10. fp = z @ fp_w^T + fp_b -> sB (stride Dm), then row-normalize
    for (int jg = 0; jg < 2; ++jg)
        gemm64(sA, Dm, 0, g_fpT, nullptr, 128, 0, jg * 64, 3,
               fpb, nullptr, sB, Dm, jg * 64, false, false, sW);
    __syncthreads();
    {
        const int wid = tid >> 5, lane = tid & 31;
        for (int r = wid; r < ROWSn; r += 8) {
            float ss = 0.f;
            float v[4];
#pragma unroll
            for (int e = 0; e < 4; ++e) {
                v[e] = sB[r * Dm + lane + e * 32];
                ss += v[e] * v[e];
            }
#pragma unroll
            for (int o = 16; o; o >>= 1) ss += __shfl_xor_sync(0xffffffffu, ss, o);
            float inv = 1.f / fmaxf(sqrtf(ss), 1e-12f);
#pragma unroll
            for (int e = 0; e < 4; ++e)
                out[(size_t)3 * B + (size_t)(r0 + r) * 128 + lane + e * 32] = v[e] * inv;
        }
    }
}

// ---------------- host ----------------
extern "C" void kernel_launch(void* const* d_in, const int* in_sizes, int n_in,
                              void* d_out, int out_size) {
    const float* perc = (const float*)d_in[0];
    const float* tech = (const float*)d_in[1];
    const float* Wp   = (const float*)d_in[2];
    const float* bp   = (const float*)d_in[3];
    const float* Wt   = (const float*)d_in[4];
    const float* bt   = (const float*)d_in[5];
    const float* in_w = (const float*)d_in[6];
    const float* in_b = (const float*)d_in[7];
    const float* out_w= (const float*)d_in[8];
    const float* out_b= (const float*)d_in[9];
    const float* f1w  = (const float*)d_in[10];
    const float* f1b  = (const float*)d_in[11];
    const float* f2w  = (const float*)d_in[12];
    const float* f2b  = (const float*)d_in[13];
    const float* ln1g = (const float*)d_in[14];
    const float* ln1b = (const float*)d_in[15];
    const float* ln2g = (const float*)d_in[16];
    const float* ln2b = (const float*)d_in[17];
    const float* c1w  = (const float*)d_in[18];
    const float* c1b  = (const float*)d_in[19];
    const float* c2w  = (const float*)d_in[20];
    const float* c2b  = (const float*)d_in[21];
    const float* fpw  = (const float*)d_in[22];
    const float* fpb  = (const float*)d_in[23];
    float* out = (float*)d_out;
    const int B = in_sizes[0] / Dm;

    void* p;
    cudaGetSymbolAddress(&p, g_WpT);  float* dWpT = (float*)p;
    cudaGetSymbolAddress(&p, g_WtT);  float* dWtT = (float*)p;
    cudaGetSymbolAddress(&p, g_inT);  float* dinT = (float*)p;
    cudaGetSymbolAddress(&p, g_outT); float* doutT = (float*)p;
    cudaGetSymbolAddress(&p, g_f1T);  float* df1T = (float*)p;
    cudaGetSymbolAddress(&p, g_f2T);  float* df2T = (float*)p;
    cudaGetSymbolAddress(&p, g_c1T);  float* dc1T = (float*)p;
    cudaGetSymbolAddress(&p, g_fpT);  float* dfpT = (float*)p;

    transpose_kernel<<<256, 256>>>(Wp,   dWpT, Dm, Dm);
    transpose_kernel<<<256, 256>>>(Wt,   dWtT, Dm, Dm);
    transpose_kernel<<<256, 256>>>(in_w, dinT, 3 * Dm, Dm);
    transpose_kernel<<<256, 256>>>(out_w,doutT, Dm, Dm);
    transpose_kernel<<<256, 256>>>(f1w,  df1T, 2 * Dm, Dm);
    transpose_kernel<<<256, 256>>>(f2w,  df2T, Dm, 2 * Dm);
    transpose_kernel<<<256, 256>>>(c1w,  dc1T, Dm, Dm);
    transpose_kernel<<<256, 256>>>(fpw,  dfpT, 128, Dm);

    cudaFuncSetAttribute(fusion_kernel,
                         cudaFuncAttributeMaxDynamicSharedMemorySize, SMEM_BYTES);
    fusion_kernel<<<B / ROWSn, NTH, SMEM_BYTES>>>(
        perc, tech, bp, bt, in_b, out_b, f1b, f2b,
        ln1g, ln1b, ln2g, ln2b, c1b, c2w, c2b, fpb, out, B);
}

// round 3
// speedup vs baseline: 1.8186x; 1.8186x over previous
#include <cuda_runtime.h>
#include <math.h>

#define Dm    192
#define ROWSn 32
#define NTH   256
#define SD    196   // stride (floats) for 192-wide activation buffers  (196 % 32 == 4)
#define SH    68    // stride for 64-wide buffers (q/k/v/ctx)           (68  % 32 == 4)
#define WTS   72    // weight tile stride: bank = 8k+n -> conflict-free B frags
#define WTILE (64 * WTS)   // 4608 floats per 64x64 tile

// ---------------- transposed (k-major, tf32-rounded) weight buffers ----------------
__device__ __align__(16) float g_WpT[192 * 192];
__device__ __align__(16) float g_WtT[192 * 192];
__device__ __align__(16) float g_inT[192 * 576];
__device__ __align__(16) float g_outT[192 * 192];
__device__ __align__(16) float g_f1T[192 * 384];
__device__ __align__(16) float g_f2T[384 * 192];
__device__ __align__(16) float g_c1T[192 * 192];
__device__ __align__(16) float g_fpT[192 * 128];

__device__ __forceinline__ unsigned f2tf(float x) {
    unsigned u;
    asm("cvt.rna.tf32.f32 %0, %1;" : "=r"(u) : "f"(x));
    return u;
}

// Single prep kernel: transpose to k-major AND round weights to tf32 (RNA).
// One launch -> ncu's "-s 5" lands on the fusion kernel during graph replay.
__global__ void prep_kernel(const float* Wp, const float* Wt, const float* in_w,
                            const float* out_w, const float* f1w, const float* f2w,
                            const float* c1w, const float* fpw) {
    const float* srcs[8] = {Wp, Wt, in_w, out_w, f1w, f2w, c1w, fpw};
    float* dsts[8] = {g_WpT, g_WtT, g_inT, g_outT, g_f1T, g_f2T, g_c1T, g_fpT};
    const int Rs[8] = {192, 192, 576, 192, 384, 192, 192, 128};
    const int Cs[8] = {192, 192, 192, 192, 192, 384, 192, 192};
#pragma unroll 1
    for (int m = 0; m < 8; ++m) {
        const float* s = srcs[m];
        float* dd = dsts[m];
        int R = Rs[m], C = Cs[m], n = R * C;
        for (int d = blockIdx.x * blockDim.x + threadIdx.x; d < n;
             d += gridDim.x * blockDim.x) {
            int k = d / R, j = d % R;              // dst[k][j] = src[j][k], rounded
            dd[d] = __uint_as_float(f2tf(s[j * C + k]));
        }
    }
}

// ---------------- tf32 tensor-core GEMM pass ----------------
// out[r][jo0+j] (+)= sum_k A[r][ka0+k] * Wkmajor[kw0+k][jw0+j], 64 cols, nk*64 k.
// Warp w: m-block = w&3 (16 rows), n-half = w>>2 (32 cols). m16n8k8 tf32 MMA.
// Dual-weight (gW2): rows 0..31 use gW/bias, rows 32..63 use gW2/bias2 (per m-block).
// permuteOut: physical row r -> token row (r<32 ? 2r : 2(r-32)+1).
__device__ __noinline__ void gemm_mma(
    const float* __restrict__ sA, int lda, int ka0,
    const float* __restrict__ gW, const float* __restrict__ gW2,
    int ldw, int kw0, int jw0, int nk,
    const float* __restrict__ bias, const float* __restrict__ bias2,
    float* __restrict__ sOut, int ldo, int jo0,
    bool accOut, bool relu, bool permuteOut, float* __restrict__ sW)
{
    const int tid = threadIdx.x;
    const int wid = tid >> 5, lane = tid & 31;
    const int mblk = wid & 3, nhalf = wid >> 2;
    const int g = lane >> 2, c = lane & 3;
    const int r0 = mblk * 16;

    float d[4][4];
#pragma unroll
    for (int nt = 0; nt < 4; ++nt)
        d[nt][0] = d[nt][1] = d[nt][2] = d[nt][3] = 0.f;

    const float* sWb = sW + ((gW2 && mblk >= 2) ? WTILE : 0);

    for (int ch = 0; ch < nk; ++ch) {
        __syncthreads();   // prior readers of sW done (also orders sA/sOut producers)
        {
            const int rr = tid >> 4;
            const int cc = (tid & 15) * 4;
#pragma unroll
            for (int rnd = 0; rnd < 4; ++rnd) {
                int k = rr + rnd * 16;
                float4 v = *(const float4*)&gW[(size_t)(kw0 + ch * 64 + k) * ldw + jw0 + cc];
                *(float4*)&sW[k * WTS + cc] = v;
            }
            if (gW2) {
#pragma unroll
                for (int rnd = 0; rnd < 4; ++rnd) {
                    int k = rr + rnd * 16;
                    float4 v = *(const float4*)&gW2[(size_t)(kw0 + ch * 64 + k) * ldw + jw0 + cc];
                    *(float4*)&sW[WTILE + k * WTS + cc] = v;
                }
            }
        }
        __syncthreads();

        const float* aRow0 = sA + (r0 + g) * lda + ka0 + ch * 64;
        const float* aRow8 = aRow0 + 8 * lda;
#pragma unroll
        for (int ks = 0; ks < 8; ++ks) {
            const int k0 = ks * 8;
            unsigned a0 = f2tf(aRow0[k0 + c]);
            unsigned a1 = f2tf(aRow8[k0 + c]);
            unsigned a2 = f2tf(aRow0[k0 + c + 4]);
            unsigned a3 = f2tf(aRow8[k0 + c + 4]);
            const float* bBase = sWb + (k0 + c) * WTS + nhalf * 32 + g;
#pragma unroll
            for (int nt = 0; nt < 4; ++nt) {
                unsigned b0 = __float_as_uint(bBase[nt * 8]);
                unsigned b1 = __float_as_uint(bBase[4 * WTS + nt * 8]);
                asm("mma.sync.aligned.m16n8k8.row.col.f32.tf32.tf32.f32 "
                    "{%0,%1,%2,%3}, {%4,%5,%6,%7}, {%8,%9}, {%0,%1,%2,%3};"
                    : "+f"(d[nt][0]), "+f"(d[nt][1]), "+f"(d[nt][2]), "+f"(d[nt][3])
                    : "r"(a0), "r"(a1), "r"(a2), "r"(a3), "r"(b0), "r"(b1));
            }
        }
    }

    // epilogue: bias / accumulate / relu / (permuted) store
    int rA = r0 + g, rB = rA + 8;
    if (permuteOut) {
        rA = (rA < 32) ? 2 * rA : 2 * (rA - 32) + 1;
        rB = (rB < 32) ? 2 * rB : 2 * (rB - 32) + 1;
    }
    const float* bptr = (bias2 && mblk >= 2) ? bias2 : bias;
#pragma unroll
    for (int nt = 0; nt < 4; ++nt) {
        int jc = nhalf * 32 + nt * 8 + 2 * c;
        float2 v0 = make_float2(d[nt][0], d[nt][1]);
        float2 v1 = make_float2(d[nt][2], d[nt][3]);
        if (bias) {
            float bx = bptr[jw0 + jc], by = bptr[jw0 + jc + 1];
            v0.x += bx; v0.y += by; v1.x += bx; v1.y += by;
        }
        float* pA = &sOut[rA * ldo + jo0 + jc];
        float* pB = &sOut[rB * ldo + jo0 + jc];
        if (accOut) {
            float2 o0 = *(float2*)pA, o1 = *(float2*)pB;
            v0.x += o0.x; v0.y += o0.y; v1.x += o1.x; v1.y += o1.y;
        }
        if (relu) {
            v0.x = fmaxf(v0.x, 0.f); v0.y = fmaxf(v0.y, 0.f);
            v1.x = fmaxf(v1.x, 0.f); v1.y = fmaxf(v1.y, 0.f);
        }
        *(float2*)pA = v0;
        *(float2*)pB = v1;
    }
}

// ---------------- attention for one head ----------------
// q at sC+0, k at sC+64*SH, v at sC+128*SH, each [64 tok][SH]; ctx overwrites q.
__device__ __forceinline__ void attention_head(float* sC, float* sMisc) {
    const int tid = threadIdx.x;
    const int wid = tid >> 5, lane = tid & 31;
    const float* q = sC;
    const float* k = sC + 64 * SH;
    const float* v = sC + 128 * SH;

#pragma unroll
    for (int ri = 0; ri < 4; ++ri) {
        int r = wid * 4 + ri;
        int t0 = 2 * r, t1 = 2 * r + 1;
        float q0a = q[t0 * SH + lane], q0b = q[t0 * SH + lane + 32];
        float q1a = q[t1 * SH + lane], q1b = q[t1 * SH + lane + 32];
        float k0a = k[t0 * SH + lane], k0b = k[t0 * SH + lane + 32];
        float k1a = k[t1 * SH + lane], k1b = k[t1 * SH + lane + 32];
        float d00 = q0a * k0a + q0b * k0b;
        float d01 = q0a * k1a + q0b * k1b;
        float d10 = q1a * k0a + q1b * k0b;
        float d11 = q1a * k1a + q1b * k1b;
#pragma unroll
        for (int o = 16; o; o >>= 1) {
            d00 += __shfl_xor_sync(0xffffffffu, d00, o);
            d01 += __shfl_xor_sync(0xffffffffu, d01, o);
            d10 += __shfl_xor_sync(0xffffffffu, d10, o);
            d11 += __shfl_xor_sync(0xffffffffu, d11, o);
        }
        if (lane == 0) {
            const float sc = 0.125f;
            d00 *= sc; d01 *= sc; d10 *= sc; d11 *= sc;
            float m0 = fmaxf(d00, d01), m1 = fmaxf(d10, d11);
            float e00 = __expf(d00 - m0), e01 = __expf(d01 - m0);
            float e10 = __expf(d10 - m1), e11 = __expf(d11 - m1);
            float i0 = 1.f / (e00 + e01), i1 = 1.f / (e10 + e11);
            sMisc[t0 * 2 + 0] = e00 * i0; sMisc[t0 * 2 + 1] = e01 * i0;
            sMisc[t1 * 2 + 0] = e10 * i1; sMisc[t1 * 2 + 1] = e11 * i1;
        }
    }
    __syncthreads();

#pragma unroll
    for (int e = 0; e < 16; ++e) {
        int idx = tid + e * 256;
        int t = idx >> 6, j = idx & 63;
        int tb = t & ~1;
        float a0 = sMisc[t * 2], a1 = sMisc[t * 2 + 1];
        sC[t * SH + j] = a0 * v[tb * SH + j] + a1 * v[(tb + 1) * SH + j];
    }
}

// ---------------- layernorm over 64 tokens of 192 (stride SD) ----------------
__device__ __forceinline__ void layernorm64(float* buf, const float* __restrict__ g,
                                            const float* __restrict__ b) {
    const int tid = threadIdx.x;
    const int wid = tid >> 5, lane = tid & 31;
    for (int t = wid; t < 64; t += 8) {
        float s = 0.f, sq = 0.f;
        float vv[6];
#pragma unroll
        for (int e = 0; e < 6; e++) {
            float x = buf[t * SD + lane + e * 32];
            vv[e] = x; s += x; sq += x * x;
        }
#pragma unroll
        for (int o = 16; o; o >>= 1) {
            s += __shfl_xor_sync(0xffffffffu, s, o);
            sq += __shfl_xor_sync(0xffffffffu, sq, o);
        }
        float mu = s * (1.f / Dm);
        float var = sq * (1.f / Dm) - mu * mu;
        float rstd = rsqrtf(var + 1e-5f);
#pragma unroll
        for (int e = 0; e < 6; e++) {
            int j = lane + e * 32;
            buf[t * SD + j] = (vv[e] - mu) * rstd * g[j] + b[j];
        }
    }
}

// smem (floats):
//  [0,     13056) R0 : input staging / q,k,v / FFN-hidden hi / z / scratch
//  [13056, 25600) A  : seq -> FFN-hidden lo -> cls1 out
//  [25600, 38144) B  : attn accum -> x -> x2 -> fp
//  [38144, 47360) W  : 2 weight tiles [64][72]
//  [47360, 47488) misc
#define SMEM_FLOATS 47488
#define SMEM_BYTES  (SMEM_FLOATS * 4)

__global__ __launch_bounds__(NTH, 1)
void fusion_kernel(const float* __restrict__ perc, const float* __restrict__ tech,
                   const float* __restrict__ bp,  const float* __restrict__ bt,
                   const float* __restrict__ in_b, const float* __restrict__ out_b,
                   const float* __restrict__ f1b, const float* __restrict__ f2b,
                   const float* __restrict__ ln1g, const float* __restrict__ ln1b,
                   const float* __restrict__ ln2g, const float* __restrict__ ln2b,
                   const float* __restrict__ c1b, const float* __restrict__ c2w,
                   const float* __restrict__ c2b, const float* __restrict__ fpb,
                   float* __restrict__ out, int B)
{
    extern __shared__ float smem[];
    float* sR0 = smem;
    float* sA = smem + 13056;
    float* sB = smem + 25600;
    float* sW = smem + 38144;
    float* sMisc = smem + 47360;

    const int tid = threadIdx.x;
    const int r0 = blockIdx.x * ROWSn;

    // 1. stage inputs GROUPED: rows 0..31 = perc, rows 32..63 = tech
    for (int idx = tid; idx < 64 * 48; idx += NTH) {
        int t = idx / 48;
        int c4 = (idx % 48) * 4;
        const float* src = (t < 32) ? perc : tech;
        int row = (t < 32) ? t : t - 32;
        float4 v = *(const float4*)&src[(size_t)(r0 + row) * Dm + c4];
        *(float4*)&sR0[t * SD + c4] = v;
    }

    // 2. projections -> sA (interleaved tokens via permuteOut)
    for (int jg = 0; jg < 3; ++jg)
        gemm_mma(sR0, SD, 0, g_WpT, g_WtT, 192, 0, jg * 64, 3,
                 bp, bt, sA, SD, jg * 64, false, false, true, sW);

    __syncthreads();
    // 3. sB = seq + out_b (residual + out-proj bias pre-added)
    for (int idx = tid; idx < 64 * 192; idx += NTH) {
        int t = idx / 192, j = idx % 192;
        sB[t * SD + j] = sA[t * SD + j] + out_b[j];
    }

    // 4. attention, head by head
    for (int h = 0; h < 3; ++h) {
        for (int part = 0; part < 3; ++part)
            gemm_mma(sA, SD, 0, g_inT, nullptr, 576, 0, part * 192 + h * 64, 3,
                     in_b, nullptr, sR0 + part * 64 * SH, SH, 0,
                     false, false, false, sW);
        __syncthreads();
        attention_head(sR0, sMisc);
        for (int jg = 0; jg < 3; ++jg)
            gemm_mma(sR0, SH, 0, g_outT, nullptr, 192, h * 64, jg * 64, 1,
                     nullptr, nullptr, sB, SD, jg * 64, true, false, false, sW);
    }
    __syncthreads();
    layernorm64(sB, ln1g, ln1b);   // x in sB

    // 5. FFN1: hidden = relu(x@W1^T+b1); cols 0..191 -> sA, cols 192..383 -> sR0
    for (int jg = 0; jg < 6; ++jg) {
        float* buf = (jg < 3) ? sA : sR0;
        gemm_mma(sB, SD, 0, g_f1T, nullptr, 384, 0, jg * 64, 3,
                 f1b, nullptr, buf, SD, (jg % 3) * 64, false, true, false, sW);
    }

    // 6. FFN2 (two K-halves, accumulate onto x in sB), then LN2
    for (int jg = 0; jg < 3; ++jg)
        gemm_mma(sA, SD, 0, g_f2T, nullptr, 192, 0, jg * 64, 3,
                 f2b, nullptr, sB, SD, jg * 64, true, false, false, sW);
    for (int jg = 0; jg < 3; ++jg)
        gemm_mma(sR0, SD, 0, g_f2T, nullptr, 192, 192, jg * 64, 3,
                 nullptr, nullptr, sB, SD, jg * 64, true, false, false, sW);
    __syncthreads();
    layernorm64(sB, ln2g, ln2b);   // x2 in sB
    __syncthreads();

    // 7. z = mean over token pair -> sR0 rows 0..31
    for (int idx = tid; idx < 32 * 192; idx += NTH) {
        int r = idx / 192, j = idx % 192;
        sR0[r * SD + j] = 0.5f * (sB[(2 * r) * SD + j] + sB[(2 * r + 1) * SD + j]);
    }

    // 8. cls1 = relu(z@W^T+b) -> sA  (rows 32..63 are garbage, ignored)
    for (int jg = 0; jg < 3; ++jg)
        gemm_mma(sR0, SD, 0, g_c1T, nullptr, 192, 0, jg * 64, 3,
                 c1b, nullptr, sA, SD, jg * 64, false, true, false, sW);
    __syncthreads();

    // 9. logits + sigmoid (fp32)
    if (tid < 96) {
        int r = tid / 3, c = tid % 3;
        float s = c2b[c];
        const float* w = c2w + c * Dm;
        const float* x = sA + r * SD;
#pragma unroll 8
        for (int kk = 0; kk < Dm; ++kk) s += x[kk] * w[kk];
        out[(size_t)c * B + r0 + r] = 1.f / (1.f + __expf(-s));
    }

    // 10. fp = z@fp_w^T + fp_b -> sB cols 0..127, then normalize rows 0..31
    for (int jg = 0; jg < 2; ++jg)
        gemm_mma(sR0, SD, 0, g_fpT, nullptr, 128, 0, jg * 64, 3,
                 fpb, nullptr, sB, SD, jg * 64, false, false, false, sW);
    __syncthreads();
    {
        const int wid = tid >> 5, lane = tid & 31;
        for (int r = wid; r < ROWSn; r += 8) {
            float ss = 0.f;
            float v[4];
#pragma unroll
            for (int e = 0; e < 4; ++e) {
                v[e] = sB[r * SD + lane + e * 32];
                ss += v[e] * v[e];
            }
#pragma unroll
            for (int o = 16; o; o >>= 1) ss += __shfl_xor_sync(0xffffffffu, ss, o);
            float inv = 1.f / fmaxf(sqrtf(ss), 1e-12f);
#pragma unroll
            for (int e = 0; e < 4; ++e)
                out[(size_t)3 * B + (size_t)(r0 + r) * 128 + lane + e * 32] = v[e] * inv;
        }
    }
}

// ---------------- host ----------------
extern "C" void kernel_launch(void* const* d_in, const int* in_sizes, int n_in,
                              void* d_out, int out_size) {
    const float* perc = (const float*)d_in[0];
    const float* tech = (const float*)d_in[1];
    const float* Wp   = (const float*)d_in[2];
    const float* bp   = (const float*)d_in[3];
    const float* Wt   = (const float*)d_in[4];
    const float* bt   = (const float*)d_in[5];
    const float* in_w = (const float*)d_in[6];
    const float* in_b = (const float*)d_in[7];
    const float* out_w= (const float*)d_in[8];
    const float* out_b= (const float*)d_in[9];
    const float* f1w  = (const float*)d_in[10];
    const float* f1b  = (const float*)d_in[11];
    const float* f2w  = (const float*)d_in[12];
    const float* f2b  = (const float*)d_in[13];
    const float* ln1g = (const float*)d_in[14];
    const float* ln1b = (const float*)d_in[15];
    const float* ln2g = (const float*)d_in[16];
    const float* ln2b = (const float*)d_in[17];
    const float* c1w  = (const float*)d_in[18];
    const float* c1b  = (const float*)d_in[19];
    const float* c2w  = (const float*)d_in[20];
    const float* c2b  = (const float*)d_in[21];
    const float* fpw  = (const float*)d_in[22];
    const float* fpb  = (const float*)d_in[23];
    float* out = (float*)d_out;
    const int B = in_sizes[0] / Dm;

    prep_kernel<<<512, 256>>>(Wp, Wt, in_w, out_w, f1w, f2w, c1w, fpw);

    cudaFuncSetAttribute(fusion_kernel,
                         cudaFuncAttributeMaxDynamicSharedMemorySize, SMEM_BYTES);
    fusion_kernel<<<B / ROWSn, NTH, SMEM_BYTES>>>(
        perc, tech, bp, bt, in_b, out_b, f1b, f2b,
        ln1g, ln1b, ln2g, ln2b, c1b, c2w, c2b, fpb, out, B);
}

// round 6
// speedup vs baseline: 2.1382x; 1.1757x over previous
#include <cuda_runtime.h>
#include <cstdint>
#include <math.h>

#define Dm    192
#define ROWSn 32
#define NTH   512
#define SD    196   // stride (floats) for 192-wide activation buffers  (196 % 32 == 4)
#define SH    68    // stride for 64-wide buffers (q/k/v/ctx)           (68  % 32 == 4)
#define WTS   72    // weight tile stride: bank = 8k+n -> conflict-free B frags
#define WTILE (64 * WTS)   // 4608 floats per 64x64 tile

// ---------------- transposed (k-major, tf32-rounded) weight buffers ----------------
__device__ __align__(16) float g_WpT[192 * 192];
__device__ __align__(16) float g_WtT[192 * 192];
__device__ __align__(16) float g_inT[192 * 576];
__device__ __align__(16) float g_outT[192 * 192];
__device__ __align__(16) float g_f1T[192 * 384];
__device__ __align__(16) float g_f2T[384 * 192];
__device__ __align__(16) float g_c1T[192 * 192];
__device__ __align__(16) float g_fpT[192 * 128];

__device__ __forceinline__ unsigned f2tf(float x) {
    unsigned u;
    asm("cvt.rna.tf32.f32 %0, %1;" : "=r"(u) : "f"(x));
    return u;
}

__device__ __forceinline__ void cp_async16(uint32_t dst, const float* src) {
    asm volatile("cp.async.cg.shared.global [%0], [%1], 16;\n" :: "r"(dst), "l"(src));
}

// Single prep kernel: transpose to k-major AND round weights to tf32 (RNA).
__global__ void prep_kernel(const float* Wp, const float* Wt, const float* in_w,
                            const float* out_w, const float* f1w, const float* f2w,
                            const float* c1w, const float* fpw) {
    const float* srcs[8] = {Wp, Wt, in_w, out_w, f1w, f2w, c1w, fpw};
    float* dsts[8] = {g_WpT, g_WtT, g_inT, g_outT, g_f1T, g_f2T, g_c1T, g_fpT};
    const int Rs[8] = {192, 192, 576, 192, 384, 192, 192, 128};
    const int Cs[8] = {192, 192, 192, 192, 192, 384, 192, 192};
#pragma unroll 1
    for (int m = 0; m < 8; ++m) {
        const float* s = srcs[m];
        float* dd = dsts[m];
        int R = Rs[m], C = Cs[m], n = R * C;
        for (int d = blockIdx.x * blockDim.x + threadIdx.x; d < n;
             d += gridDim.x * blockDim.x) {
            int k = d / R, j = d % R;              // dst[k][j] = src[j][k], rounded
            dd[d] = __uint_as_float(f2tf(s[j * C + k]));
        }
    }
}

// ---------------- tf32 tensor-core GEMM pass ----------------
// out[r][jo0+j] (+)= sum_k A[r][ka0+k] * Wkmajor[kw0+k][jw0+j], 64 cols, nk*64 k.
// 16 warps: mblk = wid&3 (16 rows), nq = wid>>2 (16 cols). m16n8k8 tf32 MMA x2.
// Weight tiles double-buffered in smem, prefetched with cp.async (one barrier
// per chunk). Dual-weight (gW2): rows 0..31 use gW/bias, 32..63 use gW2/bias2.
// permuteOut: physical row r -> token row (r<32 ? 2r : 2(r-32)+1).
__device__ __noinline__ void gemm_mma(
    const float* __restrict__ sA, int lda, int ka0,
    const float* __restrict__ gW, const float* __restrict__ gW2,
    int ldw, int kw0, int jw0, int nk,
    const float* __restrict__ bias, const float* __restrict__ bias2,
    float* __restrict__ sOut, int ldo, int jo0,
    bool accOut, bool relu, bool permuteOut, float* __restrict__ sW)
{
    const int tid = threadIdx.x;
    const int wid = tid >> 5, lane = tid & 31;
    const int mblk = wid & 3, nq = wid >> 2;   // 4 x 4 warp grid
    const int g = lane >> 2, c = lane & 3;
    const int r0 = mblk * 16;
    const uint32_t swu = (uint32_t)__cvta_generic_to_shared(sW);

    // prefetch helper: 64x64 tile (+ optional dual tile) into buffer bsel
    const int pk = tid >> 4;            // 0..31
    const int pc = (tid & 15) << 2;     // 0..60
    auto issue = [&](int ch, int bsel) {
        uint32_t dbase = swu + (unsigned)bsel * (2u * WTILE * 4u);
        const float* g0 = gW + (size_t)(kw0 + ch * 64 + pk) * ldw + jw0 + pc;
        cp_async16(dbase + (pk * WTS + pc) * 4u, g0);
        cp_async16(dbase + ((pk + 32) * WTS + pc) * 4u, g0 + 32 * (size_t)ldw);
        if (gW2) {
            const float* g1 = gW2 + (size_t)(kw0 + ch * 64 + pk) * ldw + jw0 + pc;
            cp_async16(dbase + WTILE * 4u + (pk * WTS + pc) * 4u, g1);
            cp_async16(dbase + WTILE * 4u + ((pk + 32) * WTS + pc) * 4u,
                       g1 + 32 * (size_t)ldw);
        }
        asm volatile("cp.async.commit_group;\n" ::: "memory");
    };

    float d[2][4];
#pragma unroll
    for (int nt = 0; nt < 2; ++nt)
        d[nt][0] = d[nt][1] = d[nt][2] = d[nt][3] = 0.f;

    issue(0, 0);

    for (int ch = 0; ch < nk; ++ch) {
        asm volatile("cp.async.wait_group 0;\n" ::: "memory");
        __syncthreads();   // weight buf visible; also orders prior producers of sA/sOut
        if (ch == 0 && accOut) {
            int rA = r0 + g, rB = rA + 8;   // accOut never combined with permuteOut
#pragma unroll
            for (int nt = 0; nt < 2; ++nt) {
                int jc = nq * 16 + nt * 8 + 2 * c;
                float2 o0 = *(const float2*)&sOut[rA * ldo + jo0 + jc];
                float2 o1 = *(const float2*)&sOut[rB * ldo + jo0 + jc];
                d[nt][0] += o0.x; d[nt][1] += o0.y;
                d[nt][2] += o1.x; d[nt][3] += o1.y;
            }
        }
        if (ch + 1 < nk) issue(ch + 1, (ch + 1) & 1);

        const float* sWb = sW + (ch & 1) * 2 * WTILE + ((gW2 && mblk >= 2) ? WTILE : 0);
        const float* aRow0 = sA + (r0 + g) * lda + ka0 + ch * 64;
        const float* aRow8 = aRow0 + 8 * lda;
#pragma unroll
        for (int ks = 0; ks < 8; ++ks) {
            const int k0 = ks * 8;
            unsigned a0 = f2tf(aRow0[k0 + c]);
            unsigned a1 = f2tf(aRow8[k0 + c]);
            unsigned a2 = f2tf(aRow0[k0 + c + 4]);
            unsigned a3 = f2tf(aRow8[k0 + c + 4]);
            const float* bBase = sWb + (k0 + c) * WTS + nq * 16 + g;
#pragma unroll
            for (int nt = 0; nt < 2; ++nt) {
                unsigned b0 = __float_as_uint(bBase[nt * 8]);
                unsigned b1 = __float_as_uint(bBase[4 * WTS + nt * 8]);
                asm("mma.sync.aligned.m16n8k8.row.col.f32.tf32.tf32.f32 "
                    "{%0,%1,%2,%3}, {%4,%5,%6,%7}, {%8,%9}, {%0,%1,%2,%3};"
                    : "+f"(d[nt][0]), "+f"(d[nt][1]), "+f"(d[nt][2]), "+f"(d[nt][3])
                    : "r"(a0), "r"(a1), "r"(a2), "r"(a3), "r"(b0), "r"(b1));
            }
        }
    }

    // epilogue: bias / relu / (permuted) store
    int rA = r0 + g, rB = rA + 8;
    if (permuteOut) {
        rA = (rA < 32) ? 2 * rA : 2 * (rA - 32) + 1;
        rB = (rB < 32) ? 2 * rB : 2 * (rB - 32) + 1;
    }
    const float* bptr = (bias2 && mblk >= 2) ? bias2 : bias;
#pragma unroll
    for (int nt = 0; nt < 2; ++nt) {
        int jc = nq * 16 + nt * 8 + 2 * c;
        float2 v0 = make_float2(d[nt][0], d[nt][1]);
        float2 v1 = make_float2(d[nt][2], d[nt][3]);
        if (bias) {
            float bx = bptr[jw0 + jc], by = bptr[jw0 + jc + 1];
            v0.x += bx; v0.y += by; v1.x += bx; v1.y += by;
        }
        if (relu) {
            v0.x = fmaxf(v0.x, 0.f); v0.y = fmaxf(v0.y, 0.f);
            v1.x = fmaxf(v1.x, 0.f); v1.y = fmaxf(v1.y, 0.f);
        }
        *(float2*)&sOut[rA * ldo + jo0 + jc] = v0;
        *(float2*)&sOut[rB * ldo + jo0 + jc] = v1;
    }
}

// ---------------- attention for one head (16 warps) ----------------
__device__ __forceinline__ void attention_head(float* sC, float* sMisc) {
    const int tid = threadIdx.x;
    const int wid = tid >> 5, lane = tid & 31;
    const float* q = sC;
    const float* k = sC + 64 * SH;
    const float* v = sC + 128 * SH;

#pragma unroll
    for (int ri = 0; ri < 2; ++ri) {
        int r = wid * 2 + ri;            // 32 row-pairs / 16 warps
        int t0 = 2 * r, t1 = 2 * r + 1;
        float q0a = q[t0 * SH + lane], q0b = q[t0 * SH + lane + 32];
        float q1a = q[t1 * SH + lane], q1b = q[t1 * SH + lane + 32];
        float k0a = k[t0 * SH + lane], k0b = k[t0 * SH + lane + 32];
        float k1a = k[t1 * SH + lane], k1b = k[t1 * SH + lane + 32];
        float d00 = q0a * k0a + q0b * k0b;
        float d01 = q0a * k1a + q0b * k1b;
        float d10 = q1a * k0a + q1b * k0b;
        float d11 = q1a * k1a + q1b * k1b;
#pragma unroll
        for (int o = 16; o; o >>= 1) {
            d00 += __shfl_xor_sync(0xffffffffu, d00, o);
            d01 += __shfl_xor_sync(0xffffffffu, d01, o);
            d10 += __shfl_xor_sync(0xffffffffu, d10, o);
            d11 += __shfl_xor_sync(0xffffffffu, d11, o);
        }
        if (lane == 0) {
            const float sc = 0.125f;
            d00 *= sc; d01 *= sc; d10 *= sc; d11 *= sc;
            float m0 = fmaxf(d00, d01), m1 = fmaxf(d10, d11);
            float e00 = __expf(d00 - m0), e01 = __expf(d01 - m0);
            float e10 = __expf(d10 - m1), e11 = __expf(d11 - m1);
            float i0 = 1.f / (e00 + e01), i1 = 1.f / (e10 + e11);
            sMisc[t0 * 2 + 0] = e00 * i0; sMisc[t0 * 2 + 1] = e01 * i0;
            sMisc[t1 * 2 + 0] = e10 * i1; sMisc[t1 * 2 + 1] = e11 * i1;
        }
    }
    __syncthreads();

#pragma unroll
    for (int e = 0; e < 8; ++e) {
        int idx = tid + e * NTH;
        int t = idx >> 6, j = idx & 63;
        int tb = t & ~1;
        float a0 = sMisc[t * 2], a1 = sMisc[t * 2 + 1];
        sC[t * SH + j] = a0 * v[tb * SH + j] + a1 * v[(tb + 1) * SH + j];
    }
}

// ---------------- layernorm over 64 tokens of 192 (stride SD) ----------------
__device__ __forceinline__ void layernorm64(float* buf, const float* __restrict__ g,
                                            const float* __restrict__ b) {
    const int tid = threadIdx.x;
    const int wid = tid >> 5, lane = tid & 31;
    for (int t = wid; t < 64; t += 16) {
        float s = 0.f, sq = 0.f;
        float vv[6];
#pragma unroll
        for (int e = 0; e < 6; e++) {
            float x = buf[t * SD + lane + e * 32];
            vv[e] = x; s += x; sq += x * x;
        }
#pragma unroll
        for (int o = 16; o; o >>= 1) {
            s += __shfl_xor_sync(0xffffffffu, s, o);
            sq += __shfl_xor_sync(0xffffffffu, sq, o);
        }
        float mu = s * (1.f / Dm);
        float var = sq * (1.f / Dm) - mu * mu;
        float rstd = rsqrtf(var + 1e-5f);
#pragma unroll
        for (int e = 0; e < 6; e++) {
            int j = lane + e * 32;
            buf[t * SD + j] = (vv[e] - mu) * rstd * g[j] + b[j];
        }
    }
}

// smem (floats):
//  [0,     13056) R0 : input staging / q,k,v / FFN-hidden hi / z / scratch
//  [13056, 25600) A  : seq -> FFN-hidden lo -> cls1 out
//  [25600, 38144) B  : attn accum -> x -> x2 -> fp
//  [38144, 56576) W  : 2 x (2 weight tiles [64][72])  (double buffer, dual)
//  [56576, 56704) misc
#define SMEM_FLOATS 56704
#define SMEM_BYTES  (SMEM_FLOATS * 4)

__global__ __launch_bounds__(NTH, 1)
void fusion_kernel(const float* __restrict__ perc, const float* __restrict__ tech,
                   const float* __restrict__ bp,  const float* __restrict__ bt,
                   const float* __restrict__ in_b, const float* __restrict__ out_b,
                   const float* __restrict__ f1b, const float* __restrict__ f2b,
                   const float* __restrict__ ln1g, const float* __restrict__ ln1b,
                   const float* __restrict__ ln2g, const float* __restrict__ ln2b,
                   const float* __restrict__ c1b, const float* __restrict__ c2w,
                   const float* __restrict__ c2b, const float* __restrict__ fpb,
                   float* __restrict__ out, int B)
{
    extern __shared__ float smem[];
    float* sR0 = smem;
    float* sA = smem + 13056;
    float* sB = smem + 25600;
    float* sW = smem + 38144;
    float* sMisc = smem + 56576;

    const int tid = threadIdx.x;
    const int r0 = blockIdx.x * ROWSn;

    // 1. stage inputs GROUPED: rows 0..31 = perc, rows 32..63 = tech
    for (int idx = tid; idx < 64 * 48; idx += NTH) {
        int t = idx / 48;
        int c4 = (idx % 48) * 4;
        const float* src = (t < 32) ? perc : tech;
        int row = (t < 32) ? t : t - 32;
        float4 v = *(const float4*)&src[(size_t)(r0 + row) * Dm + c4];
        *(float4*)&sR0[t * SD + c4] = v;
    }

    // 2. projections -> sA (interleaved tokens via permuteOut)
    for (int jg = 0; jg < 3; ++jg)
        gemm_mma(sR0, SD, 0, g_WpT, g_WtT, 192, 0, jg * 64, 3,
                 bp, bt, sA, SD, jg * 64, false, false, true, sW);

    __syncthreads();
    // 3. sB = seq + out_b (residual + out-proj bias pre-added)
    for (int idx = tid; idx < 64 * 192; idx += NTH) {
        int t = idx / 192, j = idx % 192;
        sB[t * SD + j] = sA[t * SD + j] + out_b[j];
    }

    // 4. attention, head by head
    for (int h = 0; h < 3; ++h) {
        for (int part = 0; part < 3; ++part)
            gemm_mma(sA, SD, 0, g_inT, nullptr, 576, 0, part * 192 + h * 64, 3,
                     in_b, nullptr, sR0 + part * 64 * SH, SH, 0,
                     false, false, false, sW);
        __syncthreads();
        attention_head(sR0, sMisc);
        for (int jg = 0; jg < 3; ++jg)
            gemm_mma(sR0, SH, 0, g_outT, nullptr, 192, h * 64, jg * 64, 1,
                     nullptr, nullptr, sB, SD, jg * 64, true, false, false, sW);
    }
    __syncthreads();
    layernorm64(sB, ln1g, ln1b);   // x in sB

    // 5. FFN1: hidden = relu(x@W1^T+b1); cols 0..191 -> sA, cols 192..383 -> sR0
    for (int jg = 0; jg < 6; ++jg) {
        float* buf = (jg < 3) ? sA : sR0;
        gemm_mma(sB, SD, 0, g_f1T, nullptr, 384, 0, jg * 64, 3,
                 f1b, nullptr, buf, SD, (jg % 3) * 64, false, true, false, sW);
    }

    // 6. FFN2 (two K-halves, accumulate onto x in sB), then LN2
    for (int jg = 0; jg < 3; ++jg)
        gemm_mma(sA, SD, 0, g_f2T, nullptr, 192, 0, jg * 64, 3,
                 f2b, nullptr, sB, SD, jg * 64, true, false, false, sW);
    for (int jg = 0; jg < 3; ++jg)
        gemm_mma(sR0, SD, 0, g_f2T, nullptr, 192, 192, jg * 64, 3,
                 nullptr, nullptr, sB, SD, jg * 64, true, false, false, sW);
    __syncthreads();
    layernorm64(sB, ln2g, ln2b);   // x2 in sB
    __syncthreads();

    // 7. z = mean over token pair -> sR0 rows 0..31
    for (int idx = tid; idx < 32 * 192; idx += NTH) {
        int r = idx / 192, j = idx % 192;
        sR0[r * SD + j] = 0.5f * (sB[(2 * r) * SD + j] + sB[(2 * r + 1) * SD + j]);
    }

    // 8. cls1 = relu(z@W^T+b) -> sA  (rows 32..63 are garbage, ignored)
    for (int jg = 0; jg < 3; ++jg)
        gemm_mma(sR0, SD, 0, g_c1T, nullptr, 192, 0, jg * 64, 3,
                 c1b, nullptr, sA, SD, jg * 64, false, true, false, sW);
    __syncthreads();

    // 9. logits + sigmoid (fp32)
    if (tid < 96) {
        int r = tid / 3, c = tid % 3;
        float s = c2b[c];
        const float* w = c2w + c * Dm;
        const float* x = sA + r * SD;
#pragma unroll 8
        for (int kk = 0; kk < Dm; ++kk) s += x[kk] * w[kk];
        out[(size_t)c * B + r0 + r] = 1.f / (1.f + __expf(-s));
    }

    // 10. fp = z@fp_w^T + fp_b -> sB cols 0..127, then normalize rows 0..31
    for (int jg = 0; jg < 2; ++jg)
        gemm_mma(sR0, SD, 0, g_fpT, nullptr, 128, 0, jg * 64, 3,
                 fpb, nullptr, sB, SD, jg * 64, false, false, false, sW);
    __syncthreads();
    {
        const int wid = tid >> 5, lane = tid & 31;
        for (int r = wid; r < ROWSn; r += 16) {
            float ss = 0.f;
            float v[4];
#pragma unroll
            for (int e = 0; e < 4; ++e) {
                v[e] = sB[r * SD + lane + e * 32];
                ss += v[e] * v[e];
            }
#pragma unroll
            for (int o = 16; o; o >>= 1) ss += __shfl_xor_sync(0xffffffffu, ss, o);
            float inv = 1.f / fmaxf(sqrtf(ss), 1e-12f);
#pragma unroll
            for (int e = 0; e < 4; ++e)
                out[(size_t)3 * B + (size_t)(r0 + r) * 128 + lane + e * 32] = v[e] * inv;
        }
    }
}

// ---------------- host ----------------
extern "C" void kernel_launch(void* const* d_in, const int* in_sizes, int n_in,
                              void* d_out, int out_size) {
    const float* perc = (const float*)d_in[0];
    const float* tech = (const float*)d_in[1];
    const float* Wp   = (const float*)d_in[2];
    const float* bp   = (const float*)d_in[3];
    const float* Wt   = (const float*)d_in[4];
    const float* bt   = (const float*)d_in[5];
    const float* in_w = (const float*)d_in[6];
    const float* in_b = (const float*)d_in[7];
    const float* out_w= (const float*)d_in[8];
    const float* out_b= (const float*)d_in[9];
    const float* f1w  = (const float*)d_in[10];
    const float* f1b  = (const float*)d_in[11];
    const float* f2w  = (const float*)d_in[12];
    const float* f2b  = (const float*)d_in[13];
    const float* ln1g = (const float*)d_in[14];
    const float* ln1b = (const float*)d_in[15];
    const float* ln2g = (const float*)d_in[16];
    const float* ln2b = (const float*)d_in[17];
    const float* c1w  = (const float*)d_in[18];
    const float* c1b  = (const float*)d_in[19];
    const float* c2w  = (const float*)d_in[20];
    const float* c2b  = (const float*)d_in[21];
    const float* fpw  = (const float*)d_in[22];
    const float* fpb  = (const float*)d_in[23];
    float* out = (float*)d_out;
    const int B = in_sizes[0] / Dm;

    prep_kernel<<<512, 256>>>(Wp, Wt, in_w, out_w, f1w, f2w, c1w, fpw);

    cudaFuncSetAttribute(fusion_kernel,
                         cudaFuncAttributeMaxDynamicSharedMemorySize, SMEM_BYTES);
    fusion_kernel<<<B / ROWSn, NTH, SMEM_BYTES>>>(
        perc, tech, bp, bt, in_b, out_b, f1b, f2b,
        ln1g, ln1b, ln2g, ln2b, c1b, c2w, c2b, fpb, out, B);
}

// round 8
// speedup vs baseline: 2.7887x; 1.3042x over previous
#include <cuda_runtime.h>
#include <cuda_fp16.h>
#include <cstdint>
#include <math.h>

#define Dm    192
#define ROWSn 32
#define NTH   512
#define SD    196    // fp32 activation stride (floats)
#define SH    68     // fp32 qkv stride (floats)
#define SDH   200    // fp16 192-wide stride (halves): 400B % 128 == 16  -> LDSM conflict-free
#define SHH   72     // fp16 64-wide stride (halves): 144B % 128 == 16
#define SHD   392    // fp16 384-wide stride (halves): 784B % 128 == 16
#define WTSH  72     // weight tile stride (halves)
#define TILEH (64 * WTSH)   // 4608 halves per 64x64 tile

// smem offsets in floats
#define OFB    0        // sB fp32 master [64][SD]            (12544)
#define OFR2   12544    // qkv fp32 / HH fp16 / cls1 out      (13312)
#define OFHA0  25856    // fp16 [64][SDH]: input -> x -> z    (6400)
#define OFHA1  32256    // fp16 [64][SDH]: seq shadow         (6400)
#define OFHC   38656    // fp16 [64][SHH]: ctx                (2304)
#define OFW    40960    // fp16 weight tiles 4 x TILEH        (9216)
#define OFMISC 50176    // softmax weights                    (128)
#define SMEM_FLOATS 50304
#define SMEM_BYTES  (SMEM_FLOATS * 4)

// ---------------- fp16 k-major weight buffers ----------------
__device__ __align__(16) __half g_hWp[192 * 192];
__device__ __align__(16) __half g_hWt[192 * 192];
__device__ __align__(16) __half g_hIn[192 * 576];
__device__ __align__(16) __half g_hOut[192 * 192];
__device__ __align__(16) __half g_hF1[192 * 384];
__device__ __align__(16) __half g_hF2[384 * 192];
__device__ __align__(16) __half g_hC1[192 * 192];
__device__ __align__(16) __half g_hFp[192 * 128];

__device__ __forceinline__ void cp_async16(uint32_t dst, const void* src) {
    asm volatile("cp.async.cg.shared.global [%0], [%1], 16;\n" :: "r"(dst), "l"(src));
}

// Single prep kernel: transpose to k-major and convert to fp16.
__global__ void prep_kernel(const float* Wp, const float* Wt, const float* in_w,
                            const float* out_w, const float* f1w, const float* f2w,
                            const float* c1w, const float* fpw) {
    const float* srcs[8] = {Wp, Wt, in_w, out_w, f1w, f2w, c1w, fpw};
    __half* dsts[8] = {g_hWp, g_hWt, g_hIn, g_hOut, g_hF1, g_hF2, g_hC1, g_hFp};
    const int Rs[8] = {192, 192, 576, 192, 384, 192, 192, 128};
    const int Cs[8] = {192, 192, 192, 192, 192, 384, 192, 192};
#pragma unroll 1
    for (int m = 0; m < 8; ++m) {
        const float* s = srcs[m];
        __half* dd = dsts[m];
        int R = Rs[m], C = Cs[m], n = R * C;
        for (int d = blockIdx.x * blockDim.x + threadIdx.x; d < n;
             d += gridDim.x * blockDim.x) {
            int k = d / R, j = d % R;              // dst[k][j] = src[j][k]
            dd[d] = __float2half(s[j * C + k]);
        }
    }
}

#define MMA16(dd, a0, a1, a2, a3, b0, b1)                                        \
    asm volatile("mma.sync.aligned.m16n8k16.row.col.f32.f16.f16.f32 "            \
                 "{%0,%1,%2,%3}, {%4,%5,%6,%7}, {%8,%9}, {%0,%1,%2,%3};"         \
                 : "+f"(dd[0]), "+f"(dd[1]), "+f"(dd[2]), "+f"(dd[3])            \
                 : "r"(a0), "r"(a1), "r"(a2), "r"(a3), "r"(b0), "r"(b1))

// ---------------- fp16 tensor-core GEMM pass ----------------
// out[r][jo0+j] (+)= sum_k A[r][ka0+k] * Wkmajor[kw0+k][jw0+j], 64 cols, nk*64 k.
// 16 warps: mblk = wid&3 (16 rows), nq = wid>>2 (16 cols). m16n8k16 f16 MMA x2
// per k16 step; A via ldmatrix.x4, B via ldmatrix.x4.trans. Weight tiles double
// buffered + cp.async prefetch. Dual-weight (gW2): rows 0..31 gW, 32..63 gW2.
// permuteOut: physical row r -> token (r<32 ? 2r : 2(r-32)+1).
__device__ __noinline__ void gemm_h(
    const __half* __restrict__ sA, int lda, int ka0,
    const __half* __restrict__ gW, const __half* __restrict__ gW2,
    int ldw, int kw0, int jw0, int nk,
    const float* __restrict__ bias, const float* __restrict__ bias2,
    float* __restrict__ outF, int ldoF,
    __half* __restrict__ outH, int ldoH, int jo0,
    bool accOut, bool relu, bool permuteOut, __half* __restrict__ sW)
{
    const int tid = threadIdx.x;
    const int wid = tid >> 5, lane = tid & 31;
    const int mblk = wid & 3, nq = wid >> 2;
    const int g = lane >> 2, c = lane & 3;
    const int r0 = mblk * 16;

    const uint32_t swu = (uint32_t)__cvta_generic_to_shared(sW);
    // A ldmatrix: lanes 0-15 rows r0..r0+15 @k, lanes 16-31 same rows @k+8
    const uint32_t aAddr0 = (uint32_t)__cvta_generic_to_shared(sA) +
        (uint32_t)((( (r0 + (lane & 15)) * lda) + ka0 + ((lane >> 4) << 3)) * 2);
    // B ldmatrix.trans: k-row = (lane&7)+(lane&8), n-col = nq*16 + (lane>>4)*8
    const int bk = (lane & 7) | (lane & 8);
    const int bn = nq * 16 + ((lane >> 4) << 3);

    // prefetch mapping: thread -> (row, 8-half segment)
    const int pr = tid >> 3;
    const int ps = (tid & 7) << 3;

    __syncthreads();   // protect weight buf 0 against previous pass's readers

    auto issue = [&](int ch, int bsel) {
        uint32_t dbase = swu + (uint32_t)(bsel * (2 * TILEH * 2));
        const __half* g0 = gW + (size_t)(kw0 + ch * 64 + pr) * ldw + jw0 + ps;
        cp_async16(dbase + (uint32_t)((pr * WTSH + ps) * 2), g0);
        if (gW2) {
            const __half* g1 = gW2 + (size_t)(kw0 + ch * 64 + pr) * ldw + jw0 + ps;
            cp_async16(dbase + (uint32_t)((TILEH + pr * WTSH + ps) * 2), g1);
        }
        asm volatile("cp.async.commit_group;\n" ::: "memory");
    };

    float d[2][4];
#pragma unroll
    for (int nt = 0; nt < 2; ++nt)
        d[nt][0] = d[nt][1] = d[nt][2] = d[nt][3] = 0.f;

    issue(0, 0);

    for (int ch = 0; ch < nk; ++ch) {
        asm volatile("cp.async.wait_group 0;\n" ::: "memory");
        __syncthreads();   // weights visible; orders prior producers of sA/outF
        if (ch == 0 && accOut) {
            int rA = r0 + g, rB = rA + 8;
#pragma unroll
            for (int nt = 0; nt < 2; ++nt) {
                int jc = nq * 16 + nt * 8 + 2 * c;
                float2 o0 = *(const float2*)&outF[rA * ldoF + jo0 + jc];
                float2 o1 = *(const float2*)&outF[rB * ldoF + jo0 + jc];
                d[nt][0] += o0.x; d[nt][1] += o0.y;
                d[nt][2] += o1.x; d[nt][3] += o1.y;
            }
        }
        if (ch + 1 < nk) issue(ch + 1, (ch + 1) & 1);

        uint32_t wb = swu +
            (uint32_t)((((ch & 1) * 2 * TILEH) + ((gW2 && mblk >= 2) ? TILEH : 0)) * 2);
        uint32_t aAddr = aAddr0 + (uint32_t)(ch * 64 * 2);
#pragma unroll
        for (int ks = 0; ks < 4; ++ks) {
            uint32_t a0, a1, a2, a3, b0, b1, b2, b3;
            asm volatile("ldmatrix.sync.aligned.m8n8.x4.shared.b16 {%0,%1,%2,%3}, [%4];"
                         : "=r"(a0), "=r"(a1), "=r"(a2), "=r"(a3)
                         : "r"(aAddr + (uint32_t)(ks * 16 * 2)));
            asm volatile("ldmatrix.sync.aligned.m8n8.x4.trans.shared.b16 {%0,%1,%2,%3}, [%4];"
                         : "=r"(b0), "=r"(b1), "=r"(b2), "=r"(b3)
                         : "r"(wb + (uint32_t)(((ks * 16 + bk) * WTSH + bn) * 2)));
            MMA16(d[0], a0, a1, a2, a3, b0, b1);
            MMA16(d[1], a0, a1, a2, a3, b2, b3);
        }
    }

    // epilogue
    int rA = r0 + g, rB = rA + 8;
    if (permuteOut) {
        rA = (rA < 32) ? 2 * rA : 2 * (rA - 32) + 1;
        rB = (rB < 32) ? 2 * rB : 2 * (rB - 32) + 1;
    }
    const float* bptr = (bias2 && mblk >= 2) ? bias2 : bias;
#pragma unroll
    for (int nt = 0; nt < 2; ++nt) {
        int jc = nq * 16 + nt * 8 + 2 * c;
        float2 v0 = make_float2(d[nt][0], d[nt][1]);
        float2 v1 = make_float2(d[nt][2], d[nt][3]);
        if (bias) {
            float bx = bptr[jw0 + jc], by = bptr[jw0 + jc + 1];
            v0.x += bx; v0.y += by; v1.x += bx; v1.y += by;
        }
        if (relu) {
            v0.x = fmaxf(v0.x, 0.f); v0.y = fmaxf(v0.y, 0.f);
            v1.x = fmaxf(v1.x, 0.f); v1.y = fmaxf(v1.y, 0.f);
        }
        if (outF) {
            *(float2*)&outF[rA * ldoF + jo0 + jc] = v0;
            *(float2*)&outF[rB * ldoF + jo0 + jc] = v1;
        }
        if (outH) {
            __half2 h0 = __floats2half2_rn(v0.x, v0.y);
            __half2 h1 = __floats2half2_rn(v1.x, v1.y);
            *(__half2*)&outH[rA * ldoH + jo0 + jc] = h0;
            *(__half2*)&outH[rB * ldoH + jo0 + jc] = h1;
        }
    }
}

// ---------------- attention for one head ----------------
// q/k/v fp32 in sQKV (stride SH, blocks of 64*SH); ctx -> fp16 ctxH (stride SHH)
__device__ __forceinline__ void attention_head(const float* sQKV, __half* ctxH,
                                               float* sMisc) {
    const int tid = threadIdx.x;
    const int wid = tid >> 5, lane = tid & 31;
    const float* q = sQKV;
    const float* k = sQKV + 64 * SH;
    const float* v = sQKV + 128 * SH;

#pragma unroll
    for (int ri = 0; ri < 2; ++ri) {
        int r = wid * 2 + ri;
        int t0 = 2 * r, t1 = 2 * r + 1;
        float q0a = q[t0 * SH + lane], q0b = q[t0 * SH + lane + 32];
        float q1a = q[t1 * SH + lane], q1b = q[t1 * SH + lane + 32];
        float k0a = k[t0 * SH + lane], k0b = k[t0 * SH + lane + 32];
        float k1a = k[t1 * SH + lane], k1b = k[t1 * SH + lane + 32];
        float d00 = q0a * k0a + q0b * k0b;
        float d01 = q0a * k1a + q0b * k1b;
        float d10 = q1a * k0a + q1b * k0b;
        float d11 = q1a * k1a + q1b * k1b;
#pragma unroll
        for (int o = 16; o; o >>= 1) {
            d00 += __shfl_xor_sync(0xffffffffu, d00, o);
            d01 += __shfl_xor_sync(0xffffffffu, d01, o);
            d10 += __shfl_xor_sync(0xffffffffu, d10, o);
            d11 += __shfl_xor_sync(0xffffffffu, d11, o);
        }
        if (lane == 0) {
            const float sc = 0.125f;
            d00 *= sc; d01 *= sc; d10 *= sc; d11 *= sc;
            float m0 = fmaxf(d00, d01), m1 = fmaxf(d10, d11);
            float e00 = __expf(d00 - m0), e01 = __expf(d01 - m0);
            float e10 = __expf(d10 - m1), e11 = __expf(d11 - m1);
            float i0 = 1.f / (e00 + e01), i1 = 1.f / (e10 + e11);
            sMisc[t0 * 2 + 0] = e00 * i0; sMisc[t0 * 2 + 1] = e01 * i0;
            sMisc[t1 * 2 + 0] = e10 * i1; sMisc[t1 * 2 + 1] = e11 * i1;
        }
    }
    __syncthreads();

#pragma unroll
    for (int e = 0; e < 8; ++e) {
        int idx = tid + e * NTH;
        int t = idx >> 6, j = idx & 63;
        int tb = t & ~1;
        float a0 = sMisc[t * 2], a1 = sMisc[t * 2 + 1];
        ctxH[t * SHH + j] =
            __float2half(a0 * v[tb * SH + j] + a1 * v[(tb + 1) * SH + j]);
    }
}

// ---------------- layernorm (fp32 master, optional fp16 shadow) ----------------
__device__ __forceinline__ void layernorm64(float* buf, const float* __restrict__ g,
                                            const float* __restrict__ b,
                                            __half* shadow) {
    const int tid = threadIdx.x;
    const int wid = tid >> 5, lane = tid & 31;
    for (int t = wid; t < 64; t += 16) {
        float s = 0.f, sq = 0.f;
        float vv[6];
#pragma unroll
        for (int e = 0; e < 6; e++) {
            float x = buf[t * SD + lane + e * 32];
            vv[e] = x; s += x; sq += x * x;
        }
#pragma unroll
        for (int o = 16; o; o >>= 1) {
            s += __shfl_xor_sync(0xffffffffu, s, o);
            sq += __shfl_xor_sync(0xffffffffu, sq, o);
        }
        float mu = s * (1.f / Dm);
        float var = sq * (1.f / Dm) - mu * mu;
        float rstd = rsqrtf(var + 1e-5f);
#pragma unroll
        for (int e = 0; e < 6; e++) {
            int j = lane + e * 32;
            float y = (vv[e] - mu) * rstd * g[j] + b[j];
            buf[t * SD + j] = y;
            if (shadow) shadow[t * SDH + j] = __float2half(y);
        }
    }
}

__global__ __launch_bounds__(NTH, 1)
void fusion_kernel(const float* __restrict__ perc, const float* __restrict__ tech,
                   const float* __restrict__ bp,  const float* __restrict__ bt,
                   const float* __restrict__ in_b, const float* __restrict__ out_b,
                   const float* __restrict__ f1b, const float* __restrict__ f2b,
                   const float* __restrict__ ln1g, const float* __restrict__ ln1b,
                   const float* __restrict__ ln2g, const float* __restrict__ ln2b,
                   const float* __restrict__ c1b, const float* __restrict__ c2w,
                   const float* __restrict__ c2b, const float* __restrict__ fpb,
                   float* __restrict__ out, int B)
{
    extern __shared__ float smem[];
    float*  sB    = smem + OFB;              // fp32 master / fp output
    float*  sR2f  = smem + OFR2;             // fp32 view: qkv / cls1 out
    __half* sHH   = (__half*)(smem + OFR2);  // fp16 view: FFN hidden
    __half* sHA0  = (__half*)(smem + OFHA0); // input -> x -> z (fp16)
    __half* sHA1  = (__half*)(smem + OFHA1); // seq shadow (fp16)
    __half* sHC   = (__half*)(smem + OFHC);  // ctx (fp16)
    __half* sWH   = (__half*)(smem + OFW);   // weight tiles
    float*  sMisc = smem + OFMISC;

    const int tid = threadIdx.x;
    const int r0 = blockIdx.x * ROWSn;

    // 1. stage inputs as fp16, GROUPED: rows 0..31 perc, 32..63 tech
    for (int idx = tid; idx < 64 * 48; idx += NTH) {
        int t = idx / 48;
        int c4 = (idx % 48) * 4;
        const float* src = (t < 32) ? perc : tech;
        int row = (t < 32) ? t : t - 32;
        float4 v = *(const float4*)&src[(size_t)(r0 + row) * Dm + c4];
        __half2 h01 = __floats2half2_rn(v.x, v.y);
        __half2 h23 = __floats2half2_rn(v.z, v.w);
        *(__half2*)&sHA0[t * SDH + c4] = h01;
        *(__half2*)&sHA0[t * SDH + c4 + 2] = h23;
    }

    // 2. projections -> sB fp32 (seq) + sHA1 fp16 shadow, token-interleaved
    for (int jg = 0; jg < 3; ++jg)
        gemm_h(sHA0, SDH, 0, g_hWp, g_hWt, 192, 0, jg * 64, 3,
               bp, bt, sB, SD, sHA1, SDH, jg * 64, false, false, true, sWH);

    __syncthreads();
    // 3. sB = seq + out_b  (pre-add out-proj bias to the residual)
    for (int idx = tid; idx < 64 * 192; idx += NTH) {
        int t = idx / 192, j = idx % 192;
        sB[t * SD + j] += out_b[j];
    }

    // 4. attention, head by head
    for (int h = 0; h < 3; ++h) {
        for (int part = 0; part < 3; ++part)
            gemm_h(sHA1, SDH, 0, g_hIn, nullptr, 576, 0, part * 192 + h * 64, 3,
                   in_b, nullptr, sR2f + part * 64 * SH, SH, nullptr, 0, 0,
                   false, false, false, sWH);
        __syncthreads();
        attention_head(sR2f, sHC, sMisc);
        for (int jg = 0; jg < 3; ++jg)
            gemm_h(sHC, SHH, 0, g_hOut, nullptr, 192, h * 64, jg * 64, 1,
                   nullptr, nullptr, sB, SD, nullptr, 0, jg * 64,
                   true, false, false, sWH);
        __syncthreads();
    }
    layernorm64(sB, ln1g, ln1b, sHA0);   // x in sB + fp16 shadow in sHA0
    __syncthreads();

    // 5. FFN1: hidden = relu(x@W1^T + b1) -> fp16 sHH [64][SHD]
    for (int jg = 0; jg < 6; ++jg)
        gemm_h(sHA0, SDH, 0, g_hF1, nullptr, 384, 0, jg * 64, 3,
               f1b, nullptr, nullptr, 0, sHH, SHD, jg * 64,
               false, true, false, sWH);

    // 6. FFN2 (two K-halves, accumulate onto x in sB), then LN2
    for (int jg = 0; jg < 3; ++jg)
        gemm_h(sHH, SHD, 0, g_hF2, nullptr, 192, 0, jg * 64, 3,
               f2b, nullptr, sB, SD, nullptr, 0, jg * 64, true, false, false, sWH);
    for (int jg = 0; jg < 3; ++jg)
        gemm_h(sHH, SHD, 192, g_hF2, nullptr, 192, 192, jg * 64, 3,
               nullptr, nullptr, sB, SD, nullptr, 0, jg * 64, true, false, false, sWH);
    __syncthreads();
    layernorm64(sB, ln2g, ln2b, nullptr);   // x2 in sB
    __syncthreads();

    // 7. z = mean over token pair -> fp16 sHA0 rows 0..31 (rows 32..63 stale/finite)
    for (int idx = tid; idx < 32 * 192; idx += NTH) {
        int r = idx / 192, j = idx % 192;
        sHA0[r * SDH + j] =
            __float2half(0.5f * (sB[(2 * r) * SD + j] + sB[(2 * r + 1) * SD + j]));
    }

    // 8. cls1 = relu(z@W^T + b) -> fp32 sR2f rows 0..31 (rows 32..63 garbage, in-bounds)
    for (int jg = 0; jg < 3; ++jg)
        gemm_h(sHA0, SDH, 0, g_hC1, nullptr, 192, 0, jg * 64, 3,
               c1b, nullptr, sR2f, SD, nullptr, 0, jg * 64, false, true, false, sWH);
    __syncthreads();

    // 9. logits + sigmoid (fp32)
    if (tid < 96) {
        int r = tid / 3, c = tid % 3;
        float s = c2b[c];
        const float* w = c2w + c * Dm;
        const float* x = sR2f + r * SD;
#pragma unroll 8
        for (int kk = 0; kk < Dm; ++kk) s += x[kk] * w[kk];
        out[(size_t)c * B + r0 + r] = 1.f / (1.f + __expf(-s));
    }

    // 10. fp = z@fp_w^T + fp_b -> sB cols 0..127 (sB free after step 7; all 64
    //     rows in-bounds: 63*SD+127 < 12544), then normalize rows 0..31
    for (int jg = 0; jg < 2; ++jg)
        gemm_h(sHA0, SDH, 0, g_hFp, nullptr, 128, 0, jg * 64, 3,
               fpb, nullptr, sB, SD, nullptr, 0, jg * 64,
               false, false, false, sWH);
    __syncthreads();
    {
        const int wid = tid >> 5, lane = tid & 31;
        for (int r = wid; r < ROWSn; r += 16) {
            float ss = 0.f;
            float v[4];
#pragma unroll
            for (int e = 0; e < 4; ++e) {
                v[e] = sB[r * SD + lane + e * 32];
                ss += v[e] * v[e];
            }
#pragma unroll
            for (int o = 16; o; o >>= 1) ss += __shfl_xor_sync(0xffffffffu, ss, o);
            float inv = 1.f / fmaxf(sqrtf(ss), 1e-12f);
#pragma unroll
            for (int e = 0; e < 4; ++e)
                out[(size_t)3 * B + (size_t)(r0 + r) * 128 + lane + e * 32] = v[e] * inv;
        }
    }
}

// ---------------- host ----------------
extern "C" void kernel_launch(void* const* d_in, const int* in_sizes, int n_in,
                              void* d_out, int out_size) {
    const float* perc = (const float*)d_in[0];
    const float* tech = (const float*)d_in[1];
    const float* Wp   = (const float*)d_in[2];
    const float* bp   = (const float*)d_in[3];
    const float* Wt   = (const float*)d_in[4];
    const float* bt   = (const float*)d_in[5];
    const float* in_w = (const float*)d_in[6];
    const float* in_b = (const float*)d_in[7];
    const float* out_w= (const float*)d_in[8];
    const float* out_b= (const float*)d_in[9];
    const float* f1w  = (const float*)d_in[10];
    const float* f1b  = (const float*)d_in[11];
    const float* f2w  = (const float*)d_in[12];
    const float* f2b  = (const float*)d_in[13];
    const float* ln1g = (const float*)d_in[14];
    const float* ln1b = (const float*)d_in[15];
    const float* ln2g = (const float*)d_in[16];
    const float* ln2b = (const float*)d_in[17];
    const float* c1w  = (const float*)d_in[18];
    const float* c1b  = (const float*)d_in[19];
    const float* c2w  = (const float*)d_in[20];
    const float* c2b  = (const float*)d_in[21];
    const float* fpw  = (const float*)d_in[22];
    const float* fpb  = (const float*)d_in[23];
    float* out = (float*)d_out;
    const int B = in_sizes[0] / Dm;

    prep_kernel<<<512, 256>>>(Wp, Wt, in_w, out_w, f1w, f2w, c1w, fpw);

    cudaFuncSetAttribute(fusion_kernel,
                         cudaFuncAttributeMaxDynamicSharedMemorySize, SMEM_BYTES);
    fusion_kernel<<<B / ROWSn, NTH, SMEM_BYTES>>>(
        perc, tech, bp, bt, in_b, out_b, f1b, f2b,
        ln1g, ln1b, ln2g, ln2b, c1b, c2w, c2b, fpb, out, B);
}

// round 10
// speedup vs baseline: 3.1361x; 1.1246x over previous
#include <cuda_runtime.h>
#include <cuda_fp16.h>
#include <cstdint>
#include <math.h>

#define Dm    192
#define ROWSn 32
#define NTH   512
#define SD    196    // fp32 activation stride (floats)
#define SH    68     // fp32 qkv stride (floats)
#define SDH   200    // fp16 192-wide stride (halves): 400B % 128 == 16 -> LDSM conflict-free
#define SHD   392    // fp16 384-wide stride (halves): 784B % 128 == 16
#define WTSH  72     // weight tile stride (halves)
#define TILEH (64 * WTSH)   // 4608 halves per 64x64 tile

// smem offsets in floats
#define OFB    0        // sB fp32 master [64][SD]                  (12544)
#define OFR2   12544    // qkv fp32 / FFN hidden fp16 / cls1 out    (13056)
#define OFHA0  25600    // fp16 [64][SDH]: input -> x -> z          (6400)
#define OFHA1  32000    // fp16 [64][SDH]: seq shadow               (6400)
#define OFHC   38400    // fp16 [64][SDH]: ctx (all heads)          (6400)
#define OFW    44800    // fp16 weight tiles 4 x TILEH              (9216)
#define OFMISC 54016    // softmax weights                          (128)
#define SMEM_FLOATS 54144
#define SMEM_BYTES  (SMEM_FLOATS * 4)

// ---------------- fp16 k-major weight buffers ----------------
__device__ __align__(16) __half g_hWp[192 * 192];
__device__ __align__(16) __half g_hWt[192 * 192];
__device__ __align__(16) __half g_hIn[192 * 576];
__device__ __align__(16) __half g_hOut[192 * 192];
__device__ __align__(16) __half g_hF1[192 * 384];
__device__ __align__(16) __half g_hF2[384 * 192];
__device__ __align__(16) __half g_hC1[192 * 192];
__device__ __align__(16) __half g_hFp[192 * 128];

__device__ __forceinline__ void cp_async16(uint32_t dst, const void* src) {
    asm volatile("cp.async.cg.shared.global [%0], [%1], 16;\n" :: "r"(dst), "l"(src));
}

// Single prep kernel: transpose to k-major and convert to fp16.
__global__ void prep_kernel(const float* Wp, const float* Wt, const float* in_w,
                            const float* out_w, const float* f1w, const float* f2w,
                            const float* c1w, const float* fpw) {
    const float* srcs[8] = {Wp, Wt, in_w, out_w, f1w, f2w, c1w, fpw};
    __half* dsts[8] = {g_hWp, g_hWt, g_hIn, g_hOut, g_hF1, g_hF2, g_hC1, g_hFp};
    const int Rs[8] = {192, 192, 576, 192, 384, 192, 192, 128};
    const int Cs[8] = {192, 192, 192, 192, 192, 384, 192, 192};
#pragma unroll 1
    for (int m = 0; m < 8; ++m) {
        const float* s = srcs[m];
        __half* dd = dsts[m];
        int R = Rs[m], C = Cs[m], n = R * C;
        for (int d = blockIdx.x * blockDim.x + threadIdx.x; d < n;
             d += gridDim.x * blockDim.x) {
            int k = d / R, j = d % R;              // dst[k][j] = src[j][k]
            dd[d] = __float2half(s[j * C + k]);
        }
    }
}

#define MMA16(dd, a0, a1, a2, a3, b0, b1)                                        \
    asm volatile("mma.sync.aligned.m16n8k16.row.col.f32.f16.f16.f32 "            \
                 "{%0,%1,%2,%3}, {%4,%5,%6,%7}, {%8,%9}, {%0,%1,%2,%3};"         \
                 : "+f"(dd[0]), "+f"(dd[1]), "+f"(dd[2]), "+f"(dd[3])            \
                 : "r"(a0), "r"(a1), "r"(a2), "r"(a3), "r"(b0), "r"(b1))

// ---------------- fp16 tensor-core GEMM pass ----------------
// out[r][jo0+j] (+)= sum_k A[r][ka0+k] * Wkmajor[kw0+k][jw0+j], 64 cols, nk*64 k.
// 16 warps: mblk = wid&3 (16 rows), nq = wid>>2 (16 cols). m16n8k16 f16 MMA x2.
// Non-dual: 3-stage weight pipeline (issue 0,1 upfront; refill ch+2; wait_group 1)
// so chunk data is requested ~2 chunks ahead. Dual (gW2, proj only): 2-stage pairs,
// depth-1. Dual: rows 0..31 gW/bias, rows 32..63 gW2/bias2.
// permuteOut: physical row r -> token (r<32 ? 2r : 2(r-32)+1).
__device__ __noinline__ void gemm_h(
    const __half* __restrict__ sA, int lda, int ka0,
    const __half* __restrict__ gW, const __half* __restrict__ gW2,
    int ldw, int kw0, int jw0, int nk,
    const float* __restrict__ bias, const float* __restrict__ bias2,
    float* __restrict__ outF, int ldoF,
    __half* __restrict__ outH, int ldoH, int jo0,
    bool accOut, bool relu, bool permuteOut, __half* __restrict__ sW)
{
    const int tid = threadIdx.x;
    const int wid = tid >> 5, lane = tid & 31;
    const int mblk = wid & 3, nq = wid >> 2;
    const int g = lane >> 2, c = lane & 3;
    const int r0 = mblk * 16;
    const bool dual = (gW2 != nullptr);

    const uint32_t swu = (uint32_t)__cvta_generic_to_shared(sW);
    const uint32_t aAddr0 = (uint32_t)__cvta_generic_to_shared(sA) +
        (uint32_t)((( (r0 + (lane & 15)) * lda) + ka0 + ((lane >> 4) << 3)) * 2);
    const int bk = (lane & 7) | (lane & 8);
    const int bn = nq * 16 + ((lane >> 4) << 3);

    // prefetch mapping: thread -> (row, 8-half segment)
    const int pr = tid >> 3;
    const int ps = (tid & 7) << 3;

    __syncthreads();   // protect weight tiles against previous pass's readers

    auto issue = [&](int ch) {
        uint32_t soff = dual ? (uint32_t)((ch & 1) * 2 * TILEH)
                             : (uint32_t)((ch % 3) * TILEH);
        uint32_t dbase = swu + soff * 2u;
        const __half* g0 = gW + (size_t)(kw0 + ch * 64 + pr) * ldw + jw0 + ps;
        cp_async16(dbase + (uint32_t)((pr * WTSH + ps) * 2), g0);
        if (dual) {
            const __half* g1 = gW2 + (size_t)(kw0 + ch * 64 + pr) * ldw + jw0 + ps;
            cp_async16(dbase + (uint32_t)((TILEH + pr * WTSH + ps) * 2), g1);
        }
        asm volatile("cp.async.commit_group;\n" ::: "memory");
    };

    float d[2][4];
#pragma unroll
    for (int nt = 0; nt < 2; ++nt)
        d[nt][0] = d[nt][1] = d[nt][2] = d[nt][3] = 0.f;

    issue(0);
    if (!dual && nk > 1) issue(1);

    for (int ch = 0; ch < nk; ++ch) {
        if (!dual && ch < nk - 1) {
            asm volatile("cp.async.wait_group 1;\n" ::: "memory");
        } else {
            asm volatile("cp.async.wait_group 0;\n" ::: "memory");
        }
        __syncthreads();   // weights visible; orders prior producers of sA/outF
        if (ch == 0 && accOut) {
            int rA = r0 + g, rB = rA + 8;
#pragma unroll
            for (int nt = 0; nt < 2; ++nt) {
                int jc = nq * 16 + nt * 8 + 2 * c;
                float2 o0 = *(const float2*)&outF[rA * ldoF + jo0 + jc];
                float2 o1 = *(const float2*)&outF[rB * ldoF + jo0 + jc];
                d[nt][0] += o0.x; d[nt][1] += o0.y;
                d[nt][2] += o1.x; d[nt][3] += o1.y;
            }
        }
        int nx = dual ? ch + 1 : ch + 2;   // refill stage last read at ch-1 (safe)
        if (nx < nk) issue(nx);

        uint32_t soff = dual
            ? (uint32_t)(((ch & 1) * 2 * TILEH) + ((mblk >= 2) ? TILEH : 0))
            : (uint32_t)((ch % 3) * TILEH);
        uint32_t wb = swu + soff * 2u;
        uint32_t aAddr = aAddr0 + (uint32_t)(ch * 64 * 2);
#pragma unroll
        for (int ks = 0; ks < 4; ++ks) {
            uint32_t a0, a1, a2, a3, b0, b1, b2, b3;
            asm volatile("ldmatrix.sync.aligned.m8n8.x4.shared.b16 {%0,%1,%2,%3}, [%4];"
                         : "=r"(a0), "=r"(a1), "=r"(a2), "=r"(a3)
                         : "r"(aAddr + (uint32_t)(ks * 16 * 2)));
            asm volatile("ldmatrix.sync.aligned.m8n8.x4.trans.shared.b16 {%0,%1,%2,%3}, [%4];"
                         : "=r"(b0), "=r"(b1), "=r"(b2), "=r"(b3)
                         : "r"(wb + (uint32_t)(((ks * 16 + bk) * WTSH + bn) * 2)));
            MMA16(d[0], a0, a1, a2, a3, b0, b1);
            MMA16(d[1], a0, a1, a2, a3, b2, b3);
        }
    }

    // epilogue
    int rA = r0 + g, rB = rA + 8;
    if (permuteOut) {
        rA = (rA < 32) ? 2 * rA : 2 * (rA - 32) + 1;
        rB = (rB < 32) ? 2 * rB : 2 * (rB - 32) + 1;
    }
    const float* bptr = (dual && mblk >= 2) ? bias2 : bias;
#pragma unroll
    for (int nt = 0; nt < 2; ++nt) {
        int jc = nq * 16 + nt * 8 + 2 * c;
        float2 v0 = make_float2(d[nt][0], d[nt][1]);
        float2 v1 = make_float2(d[nt][2], d[nt][3]);
        if (bias) {
            float bx = bptr[jw0 + jc], by = bptr[jw0 + jc + 1];
            v0.x += bx; v0.y += by; v1.x += bx; v1.y += by;
        }
        if (relu) {
            v0.x = fmaxf(v0.x, 0.f); v0.y = fmaxf(v0.y, 0.f);
            v1.x = fmaxf(v1.x, 0.f); v1.y = fmaxf(v1.y, 0.f);
        }
        if (outF) {
            *(float2*)&outF[rA * ldoF + jo0 + jc] = v0;
            *(float2*)&outF[rB * ldoF + jo0 + jc] = v1;
        }
        if (outH) {
            __half2 h0 = __floats2half2_rn(v0.x, v0.y);
            __half2 h1 = __floats2half2_rn(v1.x, v1.y);
            *(__half2*)&outH[rA * ldoH + jo0 + jc] = h0;
            *(__half2*)&outH[rB * ldoH + jo0 + jc] = h1;
        }
    }
}

// ---------------- attention for one head ----------------
// q/k/v fp32 in sQKV (stride SH, blocks of 64*SH); ctx -> fp16 into ctxH
// (stride SDH) at the given column offset (head * 64).
__device__ __forceinline__ void attention_head(const float* sQKV, __half* ctxH,
                                               int jctx, float* sMisc) {
    const int tid = threadIdx.x;
    const int wid = tid >> 5, lane = tid & 31;
    const float* q = sQKV;
    const float* k = sQKV + 64 * SH;
    const float* v = sQKV + 128 * SH;

#pragma unroll
    for (int ri = 0; ri < 2; ++ri) {
        int r = wid * 2 + ri;
        int t0 = 2 * r, t1 = 2 * r + 1;
        float q0a = q[t0 * SH + lane], q0b = q[t0 * SH + lane + 32];
        float q1a = q[t1 * SH + lane], q1b = q[t1 * SH + lane + 32];
        float k0a = k[t0 * SH + lane], k0b = k[t0 * SH + lane + 32];
        float k1a = k[t1 * SH + lane], k1b = k[t1 * SH + lane + 32];
        float d00 = q0a * k0a + q0b * k0b;
        float d01 = q0a * k1a + q0b * k1b;
        float d10 = q1a * k0a + q1b * k0b;
        float d11 = q1a * k1a + q1b * k1b;
#pragma unroll
        for (int o = 16; o; o >>= 1) {
            d00 += __shfl_xor_sync(0xffffffffu, d00, o);
            d01 += __shfl_xor_sync(0xffffffffu, d01, o);
            d10 += __shfl_xor_sync(0xffffffffu, d10, o);
            d11 += __shfl_xor_sync(0xffffffffu, d11, o);
        }
        if (lane == 0) {
            const float sc = 0.125f;
            d00 *= sc; d01 *= sc; d10 *= sc; d11 *= sc;
            float m0 = fmaxf(d00, d01), m1 = fmaxf(d10, d11);
            float e00 = __expf(d00 - m0), e01 = __expf(d01 - m0);
            float e10 = __expf(d10 - m1), e11 = __expf(d11 - m1);
            float i0 = 1.f / (e00 + e01), i1 = 1.f / (e10 + e11);
            sMisc[t0 * 2 + 0] = e00 * i0; sMisc[t0 * 2 + 1] = e01 * i0;
            sMisc[t1 * 2 + 0] = e10 * i1; sMisc[t1 * 2 + 1] = e11 * i1;
        }
    }
    __syncthreads();

#pragma unroll
    for (int e = 0; e < 8; ++e) {
        int idx = tid + e * NTH;
        int t = idx >> 6, j = idx & 63;
        int tb = t & ~1;
        float a0 = sMisc[t * 2], a1 = sMisc[t * 2 + 1];
        ctxH[t * SDH + jctx + j] =
            __float2half(a0 * v[tb * SH + j] + a1 * v[(tb + 1) * SH + j]);
    }
}

// ---------------- layernorm (fp32 master, optional fp16 shadow) ----------------
__device__ __forceinline__ void layernorm64(float* buf, const float* __restrict__ g,
                                            const float* __restrict__ b,
                                            __half* shadow) {
    const int tid = threadIdx.x;
    const int wid = tid >> 5, lane = tid & 31;
    for (int t = wid; t < 64; t += 16) {
        float s = 0.f, sq = 0.f;
        float vv[6];
#pragma unroll
        for (int e = 0; e < 6; e++) {
            float x = buf[t * SD + lane + e * 32];
            vv[e] = x; s += x; sq += x * x;
        }
#pragma unroll
        for (int o = 16; o; o >>= 1) {
            s += __shfl_xor_sync(0xffffffffu, s, o);
            sq += __shfl_xor_sync(0xffffffffu, sq, o);
        }
        float mu = s * (1.f / Dm);
        float var = sq * (1.f / Dm) - mu * mu;
        float rstd = rsqrtf(var + 1e-5f);
#pragma unroll
        for (int e = 0; e < 6; e++) {
            int j = lane + e * 32;
            float y = (vv[e] - mu) * rstd * g[j] + b[j];
            buf[t * SD + j] = y;
            if (shadow) shadow[t * SDH + j] = __float2half(y);
        }
    }
}

__global__ __launch_bounds__(NTH, 1)
void fusion_kernel(const float* __restrict__ perc, const float* __restrict__ tech,
                   const float* __restrict__ bp,  const float* __restrict__ bt,
                   const float* __restrict__ in_b, const float* __restrict__ out_b,
                   const float* __restrict__ f1b, const float* __restrict__ f2b,
                   const float* __restrict__ ln1g, const float* __restrict__ ln1b,
                   const float* __restrict__ ln2g, const float* __restrict__ ln2b,
                   const float* __restrict__ c1b, const float* __restrict__ c2w,
                   const float* __restrict__ c2b, const float* __restrict__ fpb,
                   float* __restrict__ out, int B)
{
    extern __shared__ float smem[];
    float*  sB    = smem + OFB;              // fp32 master / fp output
    float*  sR2f  = smem + OFR2;             // fp32 view: qkv / cls1 out
    __half* sHH   = (__half*)(smem + OFR2);  // fp16 view: FFN hidden
    __half* sHA0  = (__half*)(smem + OFHA0); // input -> x -> z (fp16)
    __half* sHA1  = (__half*)(smem + OFHA1); // seq shadow (fp16)
    __half* sHC   = (__half*)(smem + OFHC);  // ctx all heads (fp16 [64][SDH])
    __half* sWH   = (__half*)(smem + OFW);   // weight tiles (4 x TILEH)
    float*  sMisc = smem + OFMISC;

    const int tid = threadIdx.x;
    const int r0 = blockIdx.x * ROWSn;

    // 1. stage inputs as fp16, GROUPED: rows 0..31 perc, 32..63 tech
    for (int idx = tid; idx < 64 * 48; idx += NTH) {
        int t = idx / 48;
        int c4 = (idx % 48) * 4;
        const float* src = (t < 32) ? perc : tech;
        int row = (t < 32) ? t : t - 32;
        float4 v = *(const float4*)&src[(size_t)(r0 + row) * Dm + c4];
        __half2 h01 = __floats2half2_rn(v.x, v.y);
        __half2 h23 = __floats2half2_rn(v.z, v.w);
        *(__half2*)&sHA0[t * SDH + c4] = h01;
        *(__half2*)&sHA0[t * SDH + c4 + 2] = h23;
    }

    // 2. projections -> sB fp32 (seq) + sHA1 fp16 shadow, token-interleaved
    for (int jg = 0; jg < 3; ++jg)
        gemm_h(sHA0, SDH, 0, g_hWp, g_hWt, 192, 0, jg * 64, 3,
               bp, bt, sB, SD, sHA1, SDH, jg * 64, false, false, true, sWH);

    __syncthreads();
    // 3. sB = seq + out_b  (pre-add out-proj bias to the residual)
    for (int idx = tid; idx < 64 * 192; idx += NTH) {
        int t = idx / 192, j = idx % 192;
        sB[t * SD + j] += out_b[j];
    }

    // 4. attention: per head compute q/k/v + softmax*V into ctx buffer,
    //    then ONE out-proj over the 192-wide concatenated ctx.
    for (int h = 0; h < 3; ++h) {
        for (int part = 0; part < 3; ++part)
            gemm_h(sHA1, SDH, 0, g_hIn, nullptr, 576, 0, part * 192 + h * 64, 3,
                   in_b, nullptr, sR2f + part * 64 * SH, SH, nullptr, 0, 0,
                   false, false, false, sWH);
        __syncthreads();
        attention_head(sR2f, sHC, h * 64, sMisc);
        // next pass's entry sync orders these ctx writes / qkv reuse
    }
    for (int jg = 0; jg < 3; ++jg)
        gemm_h(sHC, SDH, 0, g_hOut, nullptr, 192, 0, jg * 64, 3,
               nullptr, nullptr, sB, SD, nullptr, 0, jg * 64,
               true, false, false, sWH);
    __syncthreads();
    layernorm64(sB, ln1g, ln1b, sHA0);   // x in sB + fp16 shadow in sHA0
    __syncthreads();

    // 5. FFN1: hidden = relu(x@W1^T + b1) -> fp16 sHH [64][SHD]
    for (int jg = 0; jg < 6; ++jg)
        gemm_h(sHA0, SDH, 0, g_hF1, nullptr, 384, 0, jg * 64, 3,
               f1b, nullptr, nullptr, 0, sHH, SHD, jg * 64,
               false, true, false, sWH);

    // 6. FFN2: single nk=6 pass per output block (K=384 contiguous), then LN2
    for (int jg = 0; jg < 3; ++jg)
        gemm_h(sHH, SHD, 0, g_hF2, nullptr, 192, 0, jg * 64, 6,
               f2b, nullptr, sB, SD, nullptr, 0, jg * 64, true, false, false, sWH);
    __syncthreads();
    layernorm64(sB, ln2g, ln2b, nullptr);   // x2 in sB
    __syncthreads();

    // 7. z = mean over token pair -> fp16 sHA0 rows 0..31 (rows 32..63 stale/finite)
    for (int idx = tid; idx < 32 * 192; idx += NTH) {
        int r = idx / 192, j = idx % 192;
        sHA0[r * SDH + j] =
            __float2half(0.5f * (sB[(2 * r) * SD + j] + sB[(2 * r + 1) * SD + j]));
    }

    // 8. cls1 = relu(z@W^T + b) -> fp32 sR2f rows 0..31 (rows 32..63 garbage, in-bounds)
    for (int jg = 0; jg < 3; ++jg)
        gemm_h(sHA0, SDH, 0, g_hC1, nullptr, 192, 0, jg * 64, 3,
               c1b, nullptr, sR2f, SD, nullptr, 0, jg * 64, false, true, false, sWH);
    __syncthreads();

    // 9. logits + sigmoid (fp32)
    if (tid < 96) {
        int r = tid / 3, c = tid % 3;
        float s = c2b[c];
        const float* w = c2w + c * Dm;
        const float* x = sR2f + r * SD;
#pragma unroll 8
        for (int kk = 0; kk < Dm; ++kk) s += x[kk] * w[kk];
        out[(size_t)c * B + r0 + r] = 1.f / (1.f + __expf(-s));
    }

    // 10. fp = z@fp_w^T + fp_b -> sB cols 0..127 (sB free after step 7),
    //     then normalize rows 0..31
    for (int jg = 0; jg < 2; ++jg)
        gemm_h(sHA0, SDH, 0, g_hFp, nullptr, 128, 0, jg * 64, 3,
               fpb, nullptr, sB, SD, nullptr, 0, jg * 64,
               false, false, false, sWH);
    __syncthreads();
    {
        const int wid = tid >> 5, lane = tid & 31;
        for (int r = wid; r < ROWSn; r += 16) {
            float ss = 0.f;
            float v[4];
#pragma unroll
            for (int e = 0; e < 4; ++e) {
                v[e] = sB[r * SD + lane + e * 32];
                ss += v[e] * v[e];
            }
#pragma unroll
            for (int o = 16; o; o >>= 1) ss += __shfl_xor_sync(0xffffffffu, ss, o);
            float inv = 1.f / fmaxf(sqrtf(ss), 1e-12f);
#pragma unroll
            for (int e = 0; e < 4; ++e)
                out[(size_t)3 * B + (size_t)(r0 + r) * 128 + lane + e * 32] = v[e] * inv;
        }
    }
}

// ---------------- host ----------------
extern "C" void kernel_launch(void* const* d_in, const int* in_sizes, int n_in,
                              void* d_out, int out_size) {
    const float* perc = (const float*)d_in[0];
    const float* tech = (const float*)d_in[1];
    const float* Wp   = (const float*)d_in[2];
    const float* bp   = (const float*)d_in[3];
    const float* Wt   = (const float*)d_in[4];
    const float* bt   = (const float*)d_in[5];
    const float* in_w = (const float*)d_in[6];
    const float* in_b = (const float*)d_in[7];
    const float* out_w= (const float*)d_in[8];
    const float* out_b= (const float*)d_in[9];
    const float* f1w  = (const float*)d_in[10];
    const float* f1b  = (const float*)d_in[11];
    const float* f2w  = (const float*)d_in[12];
    const float* f2b  = (const float*)d_in[13];
    const float* ln1g = (const float*)d_in[14];
    const float* ln1b = (const float*)d_in[15];
    const float* ln2g = (const float*)d_in[16];
    const float* ln2b = (const float*)d_in[17];
    const float* c1w  = (const float*)d_in[18];
    const float* c1b  = (const float*)d_in[19];
    const float* c2w  = (const float*)d_in[20];
    const float* c2b  = (const float*)d_in[21];
    const float* fpw  = (const float*)d_in[22];
    const float* fpb  = (const float*)d_in[23];
    float* out = (float*)d_out;
    const int B = in_sizes[0] / Dm;

    prep_kernel<<<512, 256>>>(Wp, Wt, in_w, out_w, f1w, f2w, c1w, fpw);

    cudaFuncSetAttribute(fusion_kernel,
                         cudaFuncAttributeMaxDynamicSharedMemorySize, SMEM_BYTES);
    fusion_kernel<<<B / ROWSn, NTH, SMEM_BYTES>>>(
        perc, tech, bp, bt, in_b, out_b, f1b, f2b,
        ln1g, ln1b, ln2g, ln2b, c1b, c2w, c2b, fpb, out, B);
}

// round 11
// speedup vs baseline: 3.2235x; 1.0279x over previous
#include <cuda_runtime.h>
#include <cuda_fp16.h>
#include <cstdint>
#include <math.h>

#define Dm    192
#define ROWSn 32
#define NTH   512
#define SD    196     // fp32 activation stride (floats)
#define SDH   200     // fp16 192-wide stride (halves): 400B%128==16 -> LDSM conflict-free
#define SHD   392     // fp16 384-wide stride (halves): 784B%128==16
#define WTS2  200     // weight tile stride (halves)
#define TILE192 (64 * WTS2)   // 12800 halves per 64x192 tile

// smem offsets (floats)
#define OFB    0        // sB fp32 master [64][SD]                         (12544)
#define OFQ    12544    // q/ctx, k, v fp16 [64][SDH] x3 ; HH / cls1-out   (19200)
#define OFHA0  31744    // fp16 [64][SDH]: input -> x-shadow -> z          (6400)
#define OFW    38144    // fp16 weight tiles 3 x TILE192                   (19200)
#define OFMISC 57344    // softmax weights (384 used)                      (512)
#define SMEM_FLOATS 57856
#define SMEM_BYTES  (SMEM_FLOATS * 4)   // 231424 B <= 232448 max

// ---------------- fp16 k-major weight buffers ----------------
__device__ __align__(16) __half g_hWp[192 * 192];
__device__ __align__(16) __half g_hWt[192 * 192];
__device__ __align__(16) __half g_hQp[192 * 576];   // (in_w @ Wp)^T k-major
__device__ __align__(16) __half g_hQt[192 * 576];   // (in_w @ Wt)^T k-major
__device__ __align__(16) __half g_hOut[192 * 192];
__device__ __align__(16) __half g_hF1[192 * 384];
__device__ __align__(16) __half g_hF2[384 * 192];
__device__ __align__(16) __half g_hC1[192 * 192];
__device__ __align__(16) __half g_hFp2[192 * 192];  // fp_w padded to 192 cols
__device__ float g_bQp[576];                        // in_b + in_w @ bp
__device__ float g_bQt[576];                        // in_b + in_w @ bt

__device__ __forceinline__ void cp_async16(uint32_t dst, const void* src) {
    asm volatile("cp.async.cg.shared.global [%0], [%1], 16;\n" :: "r"(dst), "l"(src));
}

// Prep: transposes to k-major fp16, fp_w zero-padding, and algebraic fusion of
// the input projections into the QKV weights/biases (computed fp32, rounded once).
__global__ void prep_kernel(const float* Wp, const float* Wt, const float* in_w,
                            const float* in_b, const float* bp, const float* bt,
                            const float* out_w, const float* f1w, const float* f2w,
                            const float* c1w, const float* fpw) {
    const int t0 = blockIdx.x * blockDim.x + threadIdx.x;
    const int nthr = gridDim.x * blockDim.x;
    {
        const float* srcs[6] = {Wp, Wt, out_w, f1w, f2w, c1w};
        __half* dsts[6] = {g_hWp, g_hWt, g_hOut, g_hF1, g_hF2, g_hC1};
        const int Rs[6] = {192, 192, 192, 384, 192, 192};
        const int Cs[6] = {192, 192, 192, 192, 384, 192};
#pragma unroll 1
        for (int m = 0; m < 6; ++m) {
            int n = Rs[m] * Cs[m];
            for (int d = t0; d < n; d += nthr) {
                int k = d / Rs[m], j = d % Rs[m];
                dsts[m][d] = __float2half(srcs[m][j * Cs[m] + k]);
            }
        }
    }
    for (int d = t0; d < 192 * 192; d += nthr) {
        int k = d / 192, j = d % 192;
        g_hFp2[d] = __float2half(j < 128 ? fpw[j * 192 + k] : 0.f);
    }
    // eff[k][j] = sum_m in_w[j][m] * W{p,t}[m][k]
    for (int d = t0; d < 192 * 576; d += nthr) {
        int k = d / 576, j = d % 576;
        float sp = 0.f, st = 0.f;
        const float* iw = in_w + (size_t)j * 192;
#pragma unroll 4
        for (int m = 0; m < 192; ++m) {
            float w = iw[m];
            sp += w * Wp[m * 192 + k];
            st += w * Wt[m * 192 + k];
        }
        g_hQp[d] = __float2half(sp);
        g_hQt[d] = __float2half(st);
    }
    for (int j = t0; j < 576; j += nthr) {
        float sp = in_b[j], st = in_b[j];
        const float* iw = in_w + (size_t)j * 192;
#pragma unroll 4
        for (int m = 0; m < 192; ++m) {
            float w = iw[m];
            sp += w * bp[m];
            st += w * bt[m];
        }
        g_bQp[j] = sp;
        g_bQt[j] = st;
    }
}

#define MMA16(dd, a0, a1, a2, a3, b0, b1)                                        \
    asm volatile("mma.sync.aligned.m16n8k16.row.col.f32.f16.f16.f32 "            \
                 "{%0,%1,%2,%3}, {%4,%5,%6,%7}, {%8,%9}, {%0,%1,%2,%3};"         \
                 : "+f"(dd[0]), "+f"(dd[1]), "+f"(dd[2]), "+f"(dd[3])            \
                 : "r"(a0), "r"(a1), "r"(a2), "r"(a3), "r"(b0), "r"(b1))

// ---------------- fp16 GEMM pass, N = 192 fixed ----------------
// out[r][jo0+j] (+)= sum_k A[r][ka0+k] * W[ch*64+k][jw0+j], j in [0,192), k = nk*64.
// 16 warps: mblk=wid&3 (m16), nblk=wid>>2 (n48). Per k16: 1 A-LDSM, 3 B-LDSM, 6 MMA.
// Non-dual: 3-slot weight pipeline, prefetch 2 chunks ahead (wait_group 1).
// Dual (gW2): slots {0,1} reloaded per chunk (depth-1); rows 0..31 gW / 32..63 gW2.
__device__ __noinline__ void gemm192(
    const __half* __restrict__ sA, int lda, int ka0,
    const __half* __restrict__ gW, const __half* __restrict__ gW2,
    int ldw, int jw0, int nk,
    const float* __restrict__ bias, const float* __restrict__ bias2,
    float* __restrict__ outF, int ldoF,
    __half* __restrict__ outH, int ldoH, int jo0,
    bool accOut, bool relu, __half* __restrict__ sW)
{
    const int tid = threadIdx.x;
    const int wid = tid >> 5, lane = tid & 31;
    const int mblk = wid & 3, nblk = wid >> 2;
    const int g = lane >> 2, c = lane & 3;
    const int r0 = mblk * 16;
    const bool dual = (gW2 != nullptr);

    const uint32_t swu = (uint32_t)__cvta_generic_to_shared(sW);
    const uint32_t aAddr0 = (uint32_t)__cvta_generic_to_shared(sA) +
        (uint32_t)(((r0 + (lane & 15)) * lda + ka0 + ((lane >> 4) << 3)) * 2);
    const int bk = (lane & 7) | (lane & 8);
    const int bn0 = nblk * 48 + ((lane >> 4) << 3);

    __syncthreads();   // previous pass finished with weight slots / producers of sA, outF

    auto issue = [&](int ch) {
        uint32_t dbase = swu + (uint32_t)((dual ? 0 : (ch % 3)) * TILE192 * 2);
        const __half* gs = gW + (size_t)(ch * 64) * ldw + jw0;
#pragma unroll
        for (int i = 0; i < 3; ++i) {
            int seg = tid + i * NTH;          // 0..1535
            int row = seg / 24, col = (seg % 24) << 3;
            cp_async16(dbase + (uint32_t)((row * WTS2 + col) * 2),
                       gs + (size_t)row * ldw + col);
        }
        if (dual) {
            const __half* gs2 = gW2 + (size_t)(ch * 64) * ldw + jw0;
#pragma unroll
            for (int i = 0; i < 3; ++i) {
                int seg = tid + i * NTH;
                int row = seg / 24, col = (seg % 24) << 3;
                cp_async16(dbase + (uint32_t)((TILE192 + row * WTS2 + col) * 2),
                           gs2 + (size_t)row * ldw + col);
            }
        }
        asm volatile("cp.async.commit_group;\n" ::: "memory");
    };

    float d[6][4];
#pragma unroll
    for (int nt = 0; nt < 6; ++nt)
        d[nt][0] = d[nt][1] = d[nt][2] = d[nt][3] = 0.f;

    if (!dual) { issue(0); if (nk > 1) issue(1); }

    for (int ch = 0; ch < nk; ++ch) {
        if (dual) {
            if (ch > 0) __syncthreads();   // prior chunk's readers of slots 0/1 done
            issue(ch);
            asm volatile("cp.async.wait_group 0;\n" ::: "memory");
            __syncthreads();
        } else {
            if (ch < nk - 1)
                asm volatile("cp.async.wait_group 1;\n" ::: "memory");
            else
                asm volatile("cp.async.wait_group 0;\n" ::: "memory");
            __syncthreads();               // weights visible
            if (ch + 2 < nk) issue(ch + 2);   // slot (ch+2)%3 last read at ch-1: safe
        }
        if (ch == 0 && accOut) {
            int rA = r0 + g, rB = rA + 8;
#pragma unroll
            for (int nt = 0; nt < 6; ++nt) {
                int jc = nblk * 48 + nt * 8 + 2 * c;
                float2 o0 = *(const float2*)&outF[rA * ldoF + jo0 + jc];
                float2 o1 = *(const float2*)&outF[rB * ldoF + jo0 + jc];
                d[nt][0] += o0.x; d[nt][1] += o0.y;
                d[nt][2] += o1.x; d[nt][3] += o1.y;
            }
        }
        uint32_t wb = swu +
            (uint32_t)(((dual ? (mblk >= 2 ? 1 : 0) : (ch % 3)) * TILE192) * 2);
        uint32_t aAddr = aAddr0 + (uint32_t)(ch * 64 * 2);
#pragma unroll
        for (int ks = 0; ks < 4; ++ks) {
            uint32_t a0, a1, a2, a3;
            asm volatile("ldmatrix.sync.aligned.m8n8.x4.shared.b16 {%0,%1,%2,%3}, [%4];"
                         : "=r"(a0), "=r"(a1), "=r"(a2), "=r"(a3)
                         : "r"(aAddr + (uint32_t)(ks * 16 * 2)));
            uint32_t bBase = wb + (uint32_t)(((ks * 16 + bk) * WTS2 + bn0) * 2);
#pragma unroll
            for (int gi = 0; gi < 3; ++gi) {
                uint32_t b0, b1, b2, b3;
                asm volatile("ldmatrix.sync.aligned.m8n8.x4.trans.shared.b16 "
                             "{%0,%1,%2,%3}, [%4];"
                             : "=r"(b0), "=r"(b1), "=r"(b2), "=r"(b3)
                             : "r"(bBase + (uint32_t)(gi * 16 * 2)));
                MMA16(d[gi * 2],     a0, a1, a2, a3, b0, b1);
                MMA16(d[gi * 2 + 1], a0, a1, a2, a3, b2, b3);
            }
        }
    }

    // epilogue (rows grouped; no permutation anywhere)
    int rA = r0 + g, rB = rA + 8;
    const float* bptr = (dual && mblk >= 2) ? bias2 : bias;
#pragma unroll
    for (int nt = 0; nt < 6; ++nt) {
        int jc = nblk * 48 + nt * 8 + 2 * c;
        float2 v0 = make_float2(d[nt][0], d[nt][1]);
        float2 v1 = make_float2(d[nt][2], d[nt][3]);
        if (bias) {
            float bx = bptr[jw0 + jc], by = bptr[jw0 + jc + 1];
            v0.x += bx; v0.y += by; v1.x += bx; v1.y += by;
        }
        if (relu) {
            v0.x = fmaxf(v0.x, 0.f); v0.y = fmaxf(v0.y, 0.f);
            v1.x = fmaxf(v1.x, 0.f); v1.y = fmaxf(v1.y, 0.f);
        }
        if (outF) {
            *(float2*)&outF[rA * ldoF + jo0 + jc] = v0;
            *(float2*)&outF[rB * ldoF + jo0 + jc] = v1;
        }
        if (outH) {
            *(__half2*)&outH[rA * ldoH + jo0 + jc] = __floats2half2_rn(v0.x, v0.y);
            *(__half2*)&outH[rB * ldoH + jo0 + jc] = __floats2half2_rn(v1.x, v1.y);
        }
    }
}

// ---------------- attention, all 3 heads, grouped pairing (r, r+32) ----------------
// q/k/v fp16 [64][SDH]; ctx (fp16, stride SDH) overwrites q. sMisc: 3*128 floats.
__device__ __forceinline__ void attention_all(const __half* sQ, const __half* sK,
                                              const __half* sV, __half* ctxH,
                                              float* sMisc) {
    const int tid = threadIdx.x;
    const int wid = tid >> 5, lane = tid & 31;
#pragma unroll
    for (int uu = 0; uu < 6; ++uu) {
        int u = wid * 6 + uu;          // 96 units: 3 heads x 32 pairs
        int h = u >> 5, r = u & 31;
        int t0 = r, t1 = r + 32;
        int col = h * 64 + lane;
        float q0a = __half2float(sQ[t0 * SDH + col]);
        float q0b = __half2float(sQ[t0 * SDH + col + 32]);
        float q1a = __half2float(sQ[t1 * SDH + col]);
        float q1b = __half2float(sQ[t1 * SDH + col + 32]);
        float k0a = __half2float(sK[t0 * SDH + col]);
        float k0b = __half2float(sK[t0 * SDH + col + 32]);
        float k1a = __half2float(sK[t1 * SDH + col]);
        float k1b = __half2float(sK[t1 * SDH + col + 32]);
        float d00 = q0a * k0a + q0b * k0b;
        float d01 = q0a * k1a + q0b * k1b;
        float d10 = q1a * k0a + q1b * k0b;
        float d11 = q1a * k1a + q1b * k1b;
#pragma unroll
        for (int o = 16; o; o >>= 1) {
            d00 += __shfl_xor_sync(0xffffffffu, d00, o);
            d01 += __shfl_xor_sync(0xffffffffu, d01, o);
            d10 += __shfl_xor_sync(0xffffffffu, d10, o);
            d11 += __shfl_xor_sync(0xffffffffu, d11, o);
        }
        if (lane == 0) {
            const float sc = 0.125f;   // 1/sqrt(64)
            d00 *= sc; d01 *= sc; d10 *= sc; d11 *= sc;
            float m0 = fmaxf(d00, d01), m1 = fmaxf(d10, d11);
            float e00 = __expf(d00 - m0), e01 = __expf(d01 - m0);
            float e10 = __expf(d10 - m1), e11 = __expf(d11 - m1);
            float i0 = 1.f / (e00 + e01), i1 = 1.f / (e10 + e11);
            sMisc[h * 128 + t0 * 2 + 0] = e00 * i0;
            sMisc[h * 128 + t0 * 2 + 1] = e01 * i0;
            sMisc[h * 128 + t1 * 2 + 0] = e10 * i1;
            sMisc[h * 128 + t1 * 2 + 1] = e11 * i1;
        }
    }
    __syncthreads();   // scores ready; q reads done -> safe to overwrite q with ctx

#pragma unroll
    for (int e = 0; e < 24; ++e) {
        int idx = tid + e * NTH;       // 0..12287
        int t = idx / 192, j = idx % 192;
        int rr = t & 31, h = j >> 6;
        float w0 = sMisc[h * 128 + t * 2], w1 = sMisc[h * 128 + t * 2 + 1];
        float v0 = __half2float(sV[rr * SDH + j]);
        float v1 = __half2float(sV[(rr + 32) * SDH + j]);
        ctxH[t * SDH + j] = __float2half(w0 * v0 + w1 * v1);
    }
}

// ---------------- layernorm (fp32 master, optional fp16 shadow) ----------------
__device__ __forceinline__ void layernorm64(float* buf, const float* __restrict__ g,
                                            const float* __restrict__ b,
                                            __half* shadow) {
    const int tid = threadIdx.x;
    const int wid = tid >> 5, lane = tid & 31;
    for (int t = wid; t < 64; t += 16) {
        float s = 0.f, sq = 0.f;
        float vv[6];
#pragma unroll
        for (int e = 0; e < 6; e++) {
            float x = buf[t * SD + lane + e * 32];
            vv[e] = x; s += x; sq += x * x;
        }
#pragma unroll
        for (int o = 16; o; o >>= 1) {
            s += __shfl_xor_sync(0xffffffffu, s, o);
            sq += __shfl_xor_sync(0xffffffffu, sq, o);
        }
        float mu = s * (1.f / Dm);
        float var = sq * (1.f / Dm) - mu * mu;
        float rstd = rsqrtf(var + 1e-5f);
#pragma unroll
        for (int e = 0; e < 6; e++) {
            int j = lane + e * 32;
            float y = (vv[e] - mu) * rstd * g[j] + b[j];
            buf[t * SD + j] = y;
            if (shadow) shadow[t * SDH + j] = __float2half(y);
        }
    }
}

__global__ __launch_bounds__(NTH, 1)
void fusion_kernel(const float* __restrict__ perc, const float* __restrict__ tech,
                   const float* __restrict__ bp,  const float* __restrict__ bt,
                   const float* __restrict__ out_b,
                   const float* __restrict__ f1b, const float* __restrict__ f2b,
                   const float* __restrict__ ln1g, const float* __restrict__ ln1b,
                   const float* __restrict__ ln2g, const float* __restrict__ ln2b,
                   const float* __restrict__ c1b, const float* __restrict__ c2w,
                   const float* __restrict__ c2b, const float* __restrict__ fpb,
                   float* __restrict__ out, int B)
{
    extern __shared__ float smem[];
    float*  sB   = smem + OFB;                     // fp32 master / fp output
    __half* sQh  = (__half*)(smem + OFQ);          // q -> ctx
    __half* sKh  = (__half*)(smem + OFQ + 6400);   // k
    __half* sVh  = (__half*)(smem + OFQ + 12800);  // v
    __half* sHH  = (__half*)(smem + OFQ);          // FFN hidden [64][SHD] (overlay)
    float*  sCls = smem + OFQ;                     // cls1 out fp32 (overlay)
    __half* sHA0 = (__half*)(smem + OFHA0);        // input -> x-shadow -> z
    __half* sWH  = (__half*)(smem + OFW);          // weight slots (3 x TILE192)
    float*  sMisc = smem + OFMISC;

    const int tid = threadIdx.x;
    const int r0 = blockIdx.x * ROWSn;

    // 1. stage inputs fp16, GROUPED: rows 0..31 perc, 32..63 tech
    for (int idx = tid; idx < 64 * 48; idx += NTH) {
        int t = idx / 48;
        int c4 = (idx % 48) * 4;
        const float* src = (t < 32) ? perc : tech;
        int row = (t < 32) ? t : t - 32;
        float4 v = *(const float4*)&src[(size_t)(r0 + row) * Dm + c4];
        *(__half2*)&sHA0[t * SDH + c4] = __floats2half2_rn(v.x, v.y);
        *(__half2*)&sHA0[t * SDH + c4 + 2] = __floats2half2_rn(v.z, v.w);
    }

    // 2. proj (dual Wp/Wt) -> sB fp32 (seq, grouped)
    gemm192(sHA0, SDH, 0, g_hWp, g_hWt, 192, 0, 3,
            bp, bt, sB, SD, nullptr, 0, 0, false, false, sWH);
    __syncthreads();
    // 3. pre-add out-proj bias to the residual
    for (int idx = tid; idx < 64 * 192; idx += NTH) {
        int t = idx / 192, j = idx % 192;
        sB[t * SD + j] += out_b[j];
    }

    // 4. qkv directly from inputs via fused weights (dual by token group)
    gemm192(sHA0, SDH, 0, g_hQp, g_hQt, 576, 0, 3,
            g_bQp, g_bQt, nullptr, 0, sQh, SDH, 0, false, false, sWH);
    gemm192(sHA0, SDH, 0, g_hQp, g_hQt, 576, 192, 3,
            g_bQp, g_bQt, nullptr, 0, sKh, SDH, 0, false, false, sWH);
    gemm192(sHA0, SDH, 0, g_hQp, g_hQt, 576, 384, 3,
            g_bQp, g_bQt, nullptr, 0, sVh, SDH, 0, false, false, sWH);

    // 5. attention (all heads); ctx overwrites q
    attention_all(sQh, sKh, sVh, sQh, sMisc);

    // 6. out-proj: sB += ctx @ out_w^T
    gemm192(sQh, SDH, 0, g_hOut, nullptr, 192, 0, 3,
            nullptr, nullptr, sB, SD, nullptr, 0, 0, true, false, sWH);
    __syncthreads();
    layernorm64(sB, ln1g, ln1b, sHA0);   // x in sB + fp16 shadow in sHA0
    __syncthreads();

    // 7. FFN1 -> fp16 hidden [64][SHD] (overlays dead qkv/ctx region)
    gemm192(sHA0, SDH, 0, g_hF1, nullptr, 384, 0, 3,
            f1b, nullptr, nullptr, 0, sHH, SHD, 0, false, true, sWH);
    gemm192(sHA0, SDH, 0, g_hF1, nullptr, 384, 192, 3,
            f1b, nullptr, nullptr, 0, sHH, SHD, 192, false, true, sWH);

    // 8. FFN2 (K=384, nk=6) accumulate onto x; LN2
    gemm192(sHH, SHD, 0, g_hF2, nullptr, 192, 0, 6,
            f2b, nullptr, sB, SD, nullptr, 0, 0, true, false, sWH);
    __syncthreads();
    layernorm64(sB, ln2g, ln2b, nullptr);
    __syncthreads();

    // 9. z = mean of pair (r, r+32) -> fp16 sHA0 rows 0..31 (rows 32..63 stale x, finite)
    for (int idx = tid; idx < 32 * 192; idx += NTH) {
        int r = idx / 192, j = idx % 192;
        sHA0[r * SDH + j] =
            __float2half(0.5f * (sB[r * SD + j] + sB[(r + 32) * SD + j]));
    }

    // 10. cls1 = relu(z@W^T + b) -> fp32 sCls (rows 32..63 garbage, in-bounds)
    gemm192(sHA0, SDH, 0, g_hC1, nullptr, 192, 0, 3,
            c1b, nullptr, sCls, SD, nullptr, 0, 0, false, true, sWH);
    __syncthreads();

    // 11. logits + sigmoid
    if (tid < 96) {
        int r = tid / 3, c = tid % 3;
        float s = c2b[c];
        const float* w = c2w + c * Dm;
        const float* x = sCls + r * SD;
#pragma unroll 8
        for (int kk = 0; kk < Dm; ++kk) s += x[kk] * w[kk];
        out[(size_t)c * B + r0 + r] = 1.f / (1.f + __expf(-s));
    }

    // 12. fp = z @ fp_w^T -> sB (padded weights; bias added at normalize)
    gemm192(sHA0, SDH, 0, g_hFp2, nullptr, 192, 0, 3,
            nullptr, nullptr, sB, SD, nullptr, 0, 0, false, false, sWH);
    __syncthreads();
    {
        const int wid = tid >> 5, lane = tid & 31;
        for (int r = wid; r < ROWSn; r += 16) {
            float ss = 0.f;
            float v[4];
#pragma unroll
            for (int e = 0; e < 4; ++e) {
                int col = lane + e * 32;
                v[e] = sB[r * SD + col] + fpb[col];
                ss += v[e] * v[e];
            }
#pragma unroll
            for (int o = 16; o; o >>= 1) ss += __shfl_xor_sync(0xffffffffu, ss, o);
            float inv = 1.f / fmaxf(sqrtf(ss), 1e-12f);
#pragma unroll
            for (int e = 0; e < 4; ++e)
                out[(size_t)3 * B + (size_t)(r0 + r) * 128 + lane + e * 32] = v[e] * inv;
        }
    }
}

// ---------------- host ----------------
extern "C" void kernel_launch(void* const* d_in, const int* in_sizes, int n_in,
                              void* d_out, int out_size) {
    const float* perc = (const float*)d_in[0];
    const float* tech = (const float*)d_in[1];
    const float* Wp   = (const float*)d_in[2];
    const float* bp   = (const float*)d_in[3];
    const float* Wt   = (const float*)d_in[4];
    const float* bt   = (const float*)d_in[5];
    const float* in_w = (const float*)d_in[6];
    const float* in_b = (const float*)d_in[7];
    const float* out_w= (const float*)d_in[8];
    const float* out_b= (const float*)d_in[9];
    const float* f1w  = (const float*)d_in[10];
    const float* f1b  = (const float*)d_in[11];
    const float* f2w  = (const float*)d_in[12];
    const float* f2b  = (const float*)d_in[13];
    const float* ln1g = (const float*)d_in[14];
    const float* ln1b = (const float*)d_in[15];
    const float* ln2g = (const float*)d_in[16];
    const float* ln2b = (const float*)d_in[17];
    const float* c1w  = (const float*)d_in[18];
    const float* c1b  = (const float*)d_in[19];
    const float* c2w  = (const float*)d_in[20];
    const float* c2b  = (const float*)d_in[21];
    const float* fpw  = (const float*)d_in[22];
    const float* fpb  = (const float*)d_in[23];
    float* out = (float*)d_out;
    const int B = in_sizes[0] / Dm;

    prep_kernel<<<512, 256>>>(Wp, Wt, in_w, in_b, bp, bt,
                              out_w, f1w, f2w, c1w, fpw);

    cudaFuncSetAttribute(fusion_kernel,
                         cudaFuncAttributeMaxDynamicSharedMemorySize, SMEM_BYTES);
    fusion_kernel<<<B / ROWSn, NTH, SMEM_BYTES>>>(
        perc, tech, bp, bt, out_b, f1b, f2b,
        ln1g, ln1b, ln2g, ln2b, c1b, c2w, c2b, fpb, out, B);
}